// round 1
// baseline (speedup 1.0000x reference)
#include <cuda_runtime.h>
#include <cuda_bf16.h>
#include <cstddef>

// ============================================================================
// DeformableAttention: B=4, Lq=21760, DIM=256, NH=8, NP=4, HD=32
// Levels: (128,128),(64,64),(32,32),(16,16) -> Lv = 21760, starts 0/16384/20480/21504
// M = B*Lq = B*Lv = 87040
// ============================================================================

#define M_TOTAL 87040
#define LQ 21760

__device__ float g_value[(size_t)M_TOTAL * 256];
__device__ float g_mid[(size_t)M_TOTAL * 256];

// ----------------------------------------------------------------------------
// Tiled fp32 GEMM, K=256, N=256. BM=64, BN=64, BK=16, 256 threads, 4x4/thread.
// MODE 0: A rows gathered from the 4 feature levels, C = g_value
// MODE 1: A = g_mid, C = Cout (kernel output)
// ----------------------------------------------------------------------------
template<int MODE>
__global__ void __launch_bounds__(256) gemm_k256(
    const float* __restrict__ f0, const float* __restrict__ f1,
    const float* __restrict__ f2, const float* __restrict__ f3,
    const float* __restrict__ Wm, const float* __restrict__ bias,
    float* __restrict__ Cout)
{
    __shared__ float As[16][64];
    __shared__ float Bs[16][64];
    __shared__ const float* rowptr[64];

    const int t = threadIdx.x;
    const int m0 = blockIdx.x * 64;
    const int n0 = blockIdx.y * 64;

    if (t < 64) {
        int r = m0 + t;
        const float* p;
        if (MODE == 0) {
            int b = r / LQ;
            int l = r - b * LQ;
            if (l < 16384)      p = f0 + ((size_t)b * 16384 + l) * 256;
            else if (l < 20480) p = f1 + ((size_t)b * 4096 + (l - 16384)) * 256;
            else if (l < 21504) p = f2 + ((size_t)b * 1024 + (l - 20480)) * 256;
            else                p = f3 + ((size_t)b * 256  + (l - 21504)) * 256;
        } else {
            p = g_mid + (size_t)r * 256;
        }
        rowptr[t] = p;
    }
    __syncthreads();

    float acc[4][4] = {};
    const int ty = t >> 4, tx = t & 15;
    const int r0 = ty * 4, c0 = tx * 4;
    const int lrow = t >> 2, lkq = (t & 3) * 4;     // A-load mapping
    const int bk = t >> 4, bc = (t & 15) * 4;       // B-load mapping

    for (int k0 = 0; k0 < 256; k0 += 16) {
        // load A tile (transposed into As[k][row])
        {
            float4 a = *(const float4*)(rowptr[lrow] + k0 + lkq);
            As[lkq + 0][lrow] = a.x;
            As[lkq + 1][lrow] = a.y;
            As[lkq + 2][lrow] = a.z;
            As[lkq + 3][lrow] = a.w;
        }
        // load B tile
        {
            *(float4*)&Bs[bk][bc] = *(const float4*)(Wm + (size_t)(k0 + bk) * 256 + n0 + bc);
        }
        __syncthreads();
        #pragma unroll
        for (int k = 0; k < 16; k++) {
            float4 a = *(const float4*)&As[k][r0];
            float4 b = *(const float4*)&Bs[k][c0];
            acc[0][0] += a.x * b.x; acc[0][1] += a.x * b.y; acc[0][2] += a.x * b.z; acc[0][3] += a.x * b.w;
            acc[1][0] += a.y * b.x; acc[1][1] += a.y * b.y; acc[1][2] += a.y * b.z; acc[1][3] += a.y * b.w;
            acc[2][0] += a.z * b.x; acc[2][1] += a.z * b.y; acc[2][2] += a.z * b.z; acc[2][3] += a.z * b.w;
            acc[3][0] += a.w * b.x; acc[3][1] += a.w * b.y; acc[3][2] += a.w * b.z; acc[3][3] += a.w * b.w;
        }
        __syncthreads();
    }

    float* C = (MODE == 0) ? g_value : Cout;
    float4 bv = *(const float4*)(bias + n0 + c0);
    #pragma unroll
    for (int i = 0; i < 4; i++) {
        size_t row = (size_t)(m0 + r0 + i);
        float4 o;
        o.x = acc[i][0] + bv.x;
        o.y = acc[i][1] + bv.y;
        o.z = acc[i][2] + bv.z;
        o.w = acc[i][3] + bv.w;
        *(float4*)(C + row * 256 + n0 + c0) = o;
    }
}

// ----------------------------------------------------------------------------
// Sampling kernel: per block 16 queries, 256 threads.
// Computes offset/attention logits, softmax, nearest-neighbor indices,
// then gathers from g_value and writes the weighted sum to g_mid.
// ----------------------------------------------------------------------------
__global__ void __launch_bounds__(256) sample_kernel(
    const float* __restrict__ query,
    const float* __restrict__ refpts,
    const float* __restrict__ W_off, const float* __restrict__ b_off,
    const float* __restrict__ W_attn, const float* __restrict__ b_attn)
{
    __shared__ float Qs[16][256];         // 16 KB
    __shared__ float logit[16][96];       // 6 KB  (cols 0..63 = offsets, 64..95 = attn logits)
    __shared__ float attn_s[16][8][4];    // 2 KB
    __shared__ int   vrow[16][8][4][4];   // 8 KB  [row][h][p][lvl] -> global value row
    __shared__ float refs[16][4][2];      // reference points per row/level

    const int t = threadIdx.x;
    const long long gq0 = (long long)blockIdx.x * 16;

    // ---- load 16 query rows ----
    {
        const float4* src = (const float4*)(query + gq0 * 256);
        float4* dst = (float4*)&Qs[0][0];
        #pragma unroll
        for (int i = 0; i < 4; i++) dst[t + i * 256] = src[t + i * 256];
    }
    if (t < 128) {  // 16 rows x 4 lvl x 2 = 128 ref floats
        ((float*)refs)[t] = refpts[gq0 * 8 + t];
    }
    __syncthreads();

    // ---- logits: 16 rows x 96 cols; thread computes 2 rows x 3 cols ----
    {
        const int rg = t >> 5;     // 0..7 -> rows rg*2, rg*2+1 (constant within warp)
        const int cg = t & 31;     // 0..31 -> cols cg*3 .. cg*3+2
        float acc0[3] = {0.f, 0.f, 0.f};
        float acc1[3] = {0.f, 0.f, 0.f};
        const float* wc[3];
        int ws[3];
        #pragma unroll
        for (int j = 0; j < 3; j++) {
            int c = cg * 3 + j;
            if (c < 64) { wc[j] = W_off + c;        ws[j] = 64; }
            else        { wc[j] = W_attn + (c - 64); ws[j] = 32; }
        }
        const float* q0r = &Qs[rg * 2][0];
        const float* q1r = &Qs[rg * 2 + 1][0];
        for (int k = 0; k < 256; k++) {
            float q0 = q0r[k], q1 = q1r[k];
            #pragma unroll
            for (int j = 0; j < 3; j++) {
                float w = wc[j][k * ws[j]];
                acc0[j] += q0 * w;
                acc1[j] += q1 * w;
            }
        }
        #pragma unroll
        for (int j = 0; j < 3; j++) {
            int c = cg * 3 + j;
            float bb = (c < 64) ? b_off[c] : b_attn[c - 64];
            logit[rg * 2][c]     = acc0[j] + bb;
            logit[rg * 2 + 1][c] = acc1[j] + bb;
        }
    }
    __syncthreads();

    // ---- softmax + sample indices: thread t<128 handles one (row, head) ----
    if (t < 128) {
        const int row = t >> 3, h = t & 7;
        const long long gq = gq0 + row;
        const int b = (int)(gq / LQ);

        float l[4];
        float mx = -1e30f;
        #pragma unroll
        for (int p = 0; p < 4; p++) { l[p] = logit[row][64 + h * 4 + p]; mx = fmaxf(mx, l[p]); }
        float s = 0.f;
        #pragma unroll
        for (int p = 0; p < 4; p++) { l[p] = expf(l[p] - mx); s += l[p]; }
        float inv = 1.0f / s;
        #pragma unroll
        for (int p = 0; p < 4; p++) attn_s[row][h][p] = l[p] * inv;

        const int DIMS[4]  = {128, 64, 32, 16};
        const int START[4] = {0, 16384, 20480, 21504};
        #pragma unroll
        for (int lvl = 0; lvl < 4; lvl++) {
            float rx = refs[row][lvl][0];
            float ry = refs[row][lvl][1];
            int Wl = DIMS[lvl];
            #pragma unroll
            for (int p = 0; p < 4; p++) {
                float ox = logit[row][h * 8 + p * 2 + 0];
                float oy = logit[row][h * 8 + p * 2 + 1];
                float sx = fminf(fmaxf(rx + ox, 0.f), 1.f);
                float sy = fminf(fmaxf(ry + oy, 0.f), 1.f);
                int x0 = (int)floorf(sx * (float)(Wl - 1));
                int y0 = (int)floorf(sy * (float)(Wl - 1));
                vrow[row][h][p][lvl] = b * LQ + START[lvl] + y0 * Wl + x0;
            }
        }
    }
    __syncthreads();

    // ---- gather + weighted sum: warp h handles head h, lane = channel ----
    {
        const int h = t >> 5;     // 0..7
        const int c = t & 31;     // 0..31
        const int coff = h * 32 + c;
        for (int row = 0; row < 16; row++) {
            float a = 0.f;
            #pragma unroll
            for (int p = 0; p < 4; p++) {
                float w = attn_s[row][h][p];
                #pragma unroll
                for (int lvl = 0; lvl < 4; lvl++) {
                    a += w * g_value[(size_t)vrow[row][h][p][lvl] * 256 + coff];
                }
            }
            g_mid[(size_t)(gq0 + row) * 256 + coff] = a;
        }
    }
}

// ----------------------------------------------------------------------------
extern "C" void kernel_launch(void* const* d_in, const int* in_sizes, int n_in,
                              void* d_out, int out_size)
{
    (void)in_sizes; (void)n_in; (void)out_size;
    const float* query  = (const float*)d_in[0];
    const float* refpts = (const float*)d_in[1];
    const float* f0     = (const float*)d_in[2];
    const float* f1     = (const float*)d_in[3];
    const float* f2     = (const float*)d_in[4];
    const float* f3     = (const float*)d_in[5];
    const float* W_off  = (const float*)d_in[6];
    const float* b_off  = (const float*)d_in[7];
    const float* W_attn = (const float*)d_in[8];
    const float* b_attn = (const float*)d_in[9];
    const float* W_val  = (const float*)d_in[10];
    const float* b_val  = (const float*)d_in[11];
    const float* W_out  = (const float*)d_in[12];
    const float* b_out  = (const float*)d_in[13];
    float* out = (float*)d_out;

    dim3 ggrid(M_TOTAL / 64, 4);

    // 1) value projection (gathered rows from the 4 levels) -> g_value
    gemm_k256<0><<<ggrid, 256>>>(f0, f1, f2, f3, W_val, b_val, nullptr);

    // 2) logits + softmax + nearest-neighbor gather -> g_mid
    sample_kernel<<<M_TOTAL / 16, 256>>>(query, refpts, W_off, b_off, W_attn, b_attn);

    // 3) output projection -> out
    gemm_k256<1><<<ggrid, 256>>>(nullptr, nullptr, nullptr, nullptr, W_out, b_out, out);
}

// round 2
// speedup vs baseline: 1.3833x; 1.3833x over previous
#include <cuda_runtime.h>
#include <cuda_bf16.h>
#include <cstddef>

// ============================================================================
// DeformableAttention: B=4, Lq=21760, DIM=256, NH=8, NP=4, HD=32
// Levels: (128,128),(64,64),(32,32),(16,16) -> Lv = 21760, starts 0/16384/20480/21504
// M = B*Lq = B*Lv = 87040
// ============================================================================

#define M_TOTAL 87040
#define LQ 21760

__device__ float g_value[(size_t)M_TOTAL * 256];
__device__ float g_mid[(size_t)M_TOTAL * 256];
__device__ int   g_off_nz;   // nonzero if W_off has any nonzero element

// ---- packed fp32x2 helpers (Blackwell-only FFMA2 path) ----------------------
__device__ __forceinline__ void ffma2(unsigned long long& d,
                                      unsigned long long a,
                                      unsigned long long b) {
    asm("fma.rn.f32x2 %0, %1, %2, %0;" : "+l"(d) : "l"(a), "l"(b));
}
__device__ __forceinline__ unsigned long long dup2(float x) {
    unsigned long long r;
    asm("mov.b64 %0, {%1, %1};" : "=l"(r) : "f"(x));
    return r;
}
union U64F2 { unsigned long long u; float2 f; };

// ----------------------------------------------------------------------------
// W_off zero check: one block, OR-reduce the exponent/mantissa bits.
// ----------------------------------------------------------------------------
__global__ void __launch_bounds__(256) offcheck_kernel(const float* __restrict__ W_off)
{
    __shared__ int s[256];
    int t = threadIdx.x;
    int nz = 0;
    for (int i = t; i < 256 * 64; i += 256)
        nz |= (__float_as_int(W_off[i]) & 0x7fffffff);
    s[t] = nz;
    __syncthreads();
    for (int step = 128; step > 0; step >>= 1) {
        if (t < step) s[t] |= s[t + step];
        __syncthreads();
    }
    if (t == 0) g_off_nz = s[0];
}

// ----------------------------------------------------------------------------
// Tiled fp32 GEMM, K=256, N=256. BM=128, BN=64, BK=16, 256 threads, 8x4/thread
// using packed fma.rn.f32x2 (row pairs in the accumulator).
// MODE 0: A rows gathered from the 4 feature levels, C = g_value
// MODE 1: A = g_mid, C = Cout (kernel output)
// ----------------------------------------------------------------------------
template<int MODE>
__global__ void __launch_bounds__(256) gemm_k256(
    const float* __restrict__ f0, const float* __restrict__ f1,
    const float* __restrict__ f2, const float* __restrict__ f3,
    const float* __restrict__ Wm, const float* __restrict__ bias,
    float* __restrict__ Cout)
{
    __shared__ float As[16][128];          // k-major, rows contiguous
    __shared__ float Bs[16][64];
    __shared__ const float* rowptr[128];

    const int t = threadIdx.x;
    const int m0 = blockIdx.x * 128;
    const int n0 = blockIdx.y * 64;

    if (t < 128) {
        int r = m0 + t;
        const float* p;
        if (MODE == 0) {
            int b = r / LQ;
            int l = r - b * LQ;
            if (l < 16384)      p = f0 + ((size_t)b * 16384 + l) * 256;
            else if (l < 20480) p = f1 + ((size_t)b * 4096 + (l - 16384)) * 256;
            else if (l < 21504) p = f2 + ((size_t)b * 1024 + (l - 20480)) * 256;
            else                p = f3 + ((size_t)b * 256  + (l - 21504)) * 256;
        } else {
            p = g_mid + (size_t)r * 256;
        }
        rowptr[t] = p;
    }
    __syncthreads();

    unsigned long long acc[4][4];          // [row-pair][col], each = 2 fp32
    #pragma unroll
    for (int i = 0; i < 4; i++)
        #pragma unroll
        for (int j = 0; j < 4; j++) acc[i][j] = 0ULL;

    const int ty = t >> 4, tx = t & 15;
    const int r0 = ty * 8, c0 = tx * 4;
    const int arow = t >> 1, akq = (t & 1) * 8;    // A-load: 2 float4 per thread
    const int bk = t >> 4, bc = (t & 15) * 4;      // B-load: 1 float4 per thread

    for (int k0 = 0; k0 < 256; k0 += 16) {
        // load A tile (transposed into As[k][row])
        {
            const float* src = rowptr[arow] + k0 + akq;
            float4 a0 = *(const float4*)(src);
            float4 a1 = *(const float4*)(src + 4);
            As[akq + 0][arow] = a0.x;
            As[akq + 1][arow] = a0.y;
            As[akq + 2][arow] = a0.z;
            As[akq + 3][arow] = a0.w;
            As[akq + 4][arow] = a1.x;
            As[akq + 5][arow] = a1.y;
            As[akq + 6][arow] = a1.z;
            As[akq + 7][arow] = a1.w;
        }
        // load B tile
        *(float4*)&Bs[bk][bc] = *(const float4*)(Wm + (size_t)(k0 + bk) * 256 + n0 + bc);
        __syncthreads();

        #pragma unroll
        for (int k = 0; k < 16; k++) {
            const unsigned long long* ap = (const unsigned long long*)&As[k][r0];
            unsigned long long a01 = ap[0];
            unsigned long long a23 = ap[1];
            unsigned long long a45 = ap[2];
            unsigned long long a67 = ap[3];
            float4 b = *(const float4*)&Bs[k][c0];
            unsigned long long bx = dup2(b.x);
            unsigned long long by = dup2(b.y);
            unsigned long long bz = dup2(b.z);
            unsigned long long bw = dup2(b.w);
            ffma2(acc[0][0], a01, bx); ffma2(acc[0][1], a01, by);
            ffma2(acc[0][2], a01, bz); ffma2(acc[0][3], a01, bw);
            ffma2(acc[1][0], a23, bx); ffma2(acc[1][1], a23, by);
            ffma2(acc[1][2], a23, bz); ffma2(acc[1][3], a23, bw);
            ffma2(acc[2][0], a45, bx); ffma2(acc[2][1], a45, by);
            ffma2(acc[2][2], a45, bz); ffma2(acc[2][3], a45, bw);
            ffma2(acc[3][0], a67, bx); ffma2(acc[3][1], a67, by);
            ffma2(acc[3][2], a67, bz); ffma2(acc[3][3], a67, bw);
        }
        __syncthreads();
    }

    float* C = (MODE == 0) ? g_value : Cout;
    float4 bv = *(const float4*)(bias + n0 + c0);
    #pragma unroll
    for (int pr = 0; pr < 4; pr++) {
        U64F2 u0, u1, u2, u3;
        u0.u = acc[pr][0]; u1.u = acc[pr][1]; u2.u = acc[pr][2]; u3.u = acc[pr][3];
        size_t rlo = (size_t)(m0 + r0 + 2 * pr);
        float4 olo, ohi;
        olo.x = u0.f.x + bv.x; olo.y = u1.f.x + bv.y; olo.z = u2.f.x + bv.z; olo.w = u3.f.x + bv.w;
        ohi.x = u0.f.y + bv.x; ohi.y = u1.f.y + bv.y; ohi.z = u2.f.y + bv.z; ohi.w = u3.f.y + bv.w;
        *(float4*)(C + rlo * 256 + n0 + c0)       = olo;
        *(float4*)(C + (rlo + 1) * 256 + n0 + c0) = ohi;
    }
}

// ----------------------------------------------------------------------------
// Sampling kernel: per block 16 queries, 256 threads.
// attn logits via smem-tiled matvec; offset logits = b_off (+matvec iff W_off!=0);
// softmax; nearest-neighbor index; gather from g_value -> g_mid.
// ----------------------------------------------------------------------------
__global__ void __launch_bounds__(256) sample_kernel(
    const float* __restrict__ query,
    const float* __restrict__ refpts,
    const float* __restrict__ W_off, const float* __restrict__ b_off,
    const float* __restrict__ W_attn, const float* __restrict__ b_attn)
{
    __shared__ float Qs[16][256];         // 16 KB
    __shared__ float Ws[32][64];          // 8 KB (reused for attn [32][32] & off [32][64])
    __shared__ float logit[16][96];       // cols 0..63 offsets, 64..95 attn logits
    __shared__ float attn_s[16][8][4];
    __shared__ int   vrow[16][8][4][4];
    __shared__ float refs[16][4][2];

    const int t = threadIdx.x;
    const long long gq0 = (long long)blockIdx.x * 16;

    // ---- load 16 query rows + refs ----
    {
        const float4* src = (const float4*)(query + gq0 * 256);
        float4* dst = (float4*)&Qs[0][0];
        #pragma unroll
        for (int i = 0; i < 4; i++) dst[t + i * 256] = src[t + i * 256];
    }
    if (t < 128) ((float*)refs)[t] = refpts[gq0 * 8 + t];
    __syncthreads();

    const int row = t >> 4;      // 0..15
    const int cx  = t & 15;      // col group

    // ---- attn logits: 16 rows x 32 cols, smem-tiled over k ----
    {
        float a0 = 0.f, a1 = 0.f;
        float* WsA = &Ws[0][0];   // [32][32] view
        for (int k0 = 0; k0 < 256; k0 += 32) {
            #pragma unroll
            for (int i = 0; i < 4; i++) {
                int idx = t + i * 256;
                WsA[idx] = W_attn[(size_t)(k0 + (idx >> 5)) * 32 + (idx & 31)];
            }
            __syncthreads();
            #pragma unroll
            for (int kk = 0; kk < 32; kk++) {
                float q = Qs[row][k0 + kk];
                a0 += q * WsA[kk * 32 + cx];
                a1 += q * WsA[kk * 32 + cx + 16];
            }
            __syncthreads();
        }
        logit[row][64 + cx]      = a0 + b_attn[cx];
        logit[row][64 + cx + 16] = a1 + b_attn[cx + 16];
    }

    // ---- offset logits ----
    if (g_off_nz) {
        float a[4] = {0.f, 0.f, 0.f, 0.f};
        const int co = cx * 4;
        for (int k0 = 0; k0 < 256; k0 += 32) {
            #pragma unroll
            for (int i = 0; i < 2; i++) {
                int fi = t + i * 256;                 // float4 index, 512 total
                int kk = fi >> 4, c = (fi & 15) * 4;
                *(float4*)&Ws[kk][c] = *(const float4*)(W_off + (size_t)(k0 + kk) * 64 + c);
            }
            __syncthreads();
            #pragma unroll
            for (int kk = 0; kk < 32; kk++) {
                float q = Qs[row][k0 + kk];
                #pragma unroll
                for (int j = 0; j < 4; j++) a[j] += q * Ws[kk][co + j];
            }
            __syncthreads();
        }
        #pragma unroll
        for (int j = 0; j < 4; j++) logit[row][co + j] = a[j] + b_off[co + j];
    } else {
        // W_off == 0 -> offsets are exactly the bias
        #pragma unroll
        for (int i = 0; i < 4; i++) {
            int idx = t + i * 256;                    // 1024 = 16 rows x 64 cols
            logit[idx >> 6][idx & 63] = b_off[idx & 63];
        }
    }
    __syncthreads();

    // ---- softmax + sample indices: thread t<128 handles one (row, head) ----
    if (t < 128) {
        const int r = t >> 3, h = t & 7;
        const long long gq = gq0 + r;
        const int b = (int)(gq / LQ);

        float l[4];
        float mx = -1e30f;
        #pragma unroll
        for (int p = 0; p < 4; p++) { l[p] = logit[r][64 + h * 4 + p]; mx = fmaxf(mx, l[p]); }
        float s = 0.f;
        #pragma unroll
        for (int p = 0; p < 4; p++) { l[p] = expf(l[p] - mx); s += l[p]; }
        float inv = 1.0f / s;
        #pragma unroll
        for (int p = 0; p < 4; p++) attn_s[r][h][p] = l[p] * inv;

        const int DIMS[4]  = {128, 64, 32, 16};
        const int START[4] = {0, 16384, 20480, 21504};
        #pragma unroll
        for (int lvl = 0; lvl < 4; lvl++) {
            float rx = refs[r][lvl][0];
            float ry = refs[r][lvl][1];
            int Wl = DIMS[lvl];
            #pragma unroll
            for (int p = 0; p < 4; p++) {
                float ox = logit[r][h * 8 + p * 2 + 0];
                float oy = logit[r][h * 8 + p * 2 + 1];
                float sx = fminf(fmaxf(rx + ox, 0.f), 1.f);
                float sy = fminf(fmaxf(ry + oy, 0.f), 1.f);
                int x0 = (int)floorf(sx * (float)(Wl - 1));
                int y0 = (int)floorf(sy * (float)(Wl - 1));
                vrow[r][h][p][lvl] = b * LQ + START[lvl] + y0 * Wl + x0;
            }
        }
    }
    __syncthreads();

    // ---- gather + weighted sum: warp h handles head h, lane = channel ----
    {
        const int h = t >> 5;
        const int c = t & 31;
        const int coff = h * 32 + c;
        for (int r = 0; r < 16; r++) {
            float v[16];
            #pragma unroll
            for (int p = 0; p < 4; p++)
                #pragma unroll
                for (int lvl = 0; lvl < 4; lvl++)
                    v[p * 4 + lvl] = g_value[(size_t)vrow[r][h][p][lvl] * 256 + coff];
            float a = 0.f;
            #pragma unroll
            for (int p = 0; p < 4; p++) {
                float w = attn_s[r][h][p];
                #pragma unroll
                for (int lvl = 0; lvl < 4; lvl++) a += w * v[p * 4 + lvl];
            }
            g_mid[(size_t)(gq0 + r) * 256 + coff] = a;
        }
    }
}

// ----------------------------------------------------------------------------
extern "C" void kernel_launch(void* const* d_in, const int* in_sizes, int n_in,
                              void* d_out, int out_size)
{
    (void)in_sizes; (void)n_in; (void)out_size;
    const float* query  = (const float*)d_in[0];
    const float* refpts = (const float*)d_in[1];
    const float* f0     = (const float*)d_in[2];
    const float* f1     = (const float*)d_in[3];
    const float* f2     = (const float*)d_in[4];
    const float* f3     = (const float*)d_in[5];
    const float* W_off  = (const float*)d_in[6];
    const float* b_off  = (const float*)d_in[7];
    const float* W_attn = (const float*)d_in[8];
    const float* b_attn = (const float*)d_in[9];
    const float* W_val  = (const float*)d_in[10];
    const float* b_val  = (const float*)d_in[11];
    const float* W_out  = (const float*)d_in[12];
    const float* b_out  = (const float*)d_in[13];
    float* out = (float*)d_out;

    dim3 ggrid(M_TOTAL / 128, 4);

    offcheck_kernel<<<1, 256>>>(W_off);

    // 1) value projection (gathered rows from the 4 levels) -> g_value
    gemm_k256<0><<<ggrid, 256>>>(f0, f1, f2, f3, W_val, b_val, nullptr);

    // 2) logits + softmax + nearest-neighbor gather -> g_mid
    sample_kernel<<<M_TOTAL / 16, 256>>>(query, refpts, W_off, b_off, W_attn, b_attn);

    // 3) output projection -> out
    gemm_k256<1><<<ggrid, 256>>>(nullptr, nullptr, nullptr, nullptr, W_out, b_out, out);
}

// round 4
// speedup vs baseline: 1.4751x; 1.0664x over previous
#include <cuda_runtime.h>
#include <cuda_bf16.h>
#include <cstdint>
#include <cstddef>

// ============================================================================
// DeformableAttention: B=4, Lq=21760, DIM=256, NH=8, NP=4, HD=32
// Levels: (128,128),(64,64),(32,32),(16,16) -> Lv = 21760, starts 0/16384/20480/21504
// M = B*Lq = B*Lv = 87040
// GEMMs on tensor cores via mma.sync bf16 (3-term split, fp32 accum).
// ============================================================================

#define M_TOTAL 87040
#define LQ 21760

__device__ float g_value[(size_t)M_TOTAL * 256];
__device__ float g_mid[(size_t)M_TOTAL * 256];
__device__ int   g_off_nz;
// pre-transposed, hi/lo split weights: [slot][n*256 + k]  (slot 0=W_val, 1=W_out)
__device__ __nv_bfloat16 g_Wt_hi[2][256 * 256];
__device__ __nv_bfloat16 g_Wt_lo[2][256 * 256];

// ---------------------------------------------------------------------------
__device__ __forceinline__ uint32_t smem_to_u32(const void* p) {
    uint32_t a;
    asm("{ .reg .u64 t; cvta.to.shared.u64 t, %1; cvt.u32.u64 %0, t; }" : "=r"(a) : "l"(p));
    return a;
}
// pack two fp32 -> bf16x2 (low half = x, high half = y)
__device__ __forceinline__ uint32_t bf2(float x, float y) {
    uint32_t r;
    asm("cvt.rn.bf16x2.f32 %0, %1, %2;" : "=r"(r) : "f"(y), "f"(x));
    return r;
}
__device__ __forceinline__ void ldm_x4(uint32_t addr, uint32_t& r0, uint32_t& r1,
                                       uint32_t& r2, uint32_t& r3) {
    asm volatile("ldmatrix.sync.aligned.m8n8.x4.shared.b16 {%0,%1,%2,%3}, [%4];"
                 : "=r"(r0), "=r"(r1), "=r"(r2), "=r"(r3) : "r"(addr));
}
__device__ __forceinline__ void ldm_x2(uint32_t addr, uint32_t& r0, uint32_t& r1) {
    asm volatile("ldmatrix.sync.aligned.m8n8.x2.shared.b16 {%0,%1}, [%2];"
                 : "=r"(r0), "=r"(r1) : "r"(addr));
}
__device__ __forceinline__ void mma_bf16(float* d, const uint32_t* a, const uint32_t* b) {
    asm volatile("mma.sync.aligned.m16n8k16.row.col.f32.bf16.bf16.f32 "
                 "{%0,%1,%2,%3}, {%4,%5,%6,%7}, {%8,%9}, {%0,%1,%2,%3};"
                 : "+f"(d[0]), "+f"(d[1]), "+f"(d[2]), "+f"(d[3])
                 : "r"(a[0]), "r"(a[1]), "r"(a[2]), "r"(a[3]), "r"(b[0]), "r"(b[1]));
}

// ---------------------------------------------------------------------------
// prep: W_off zero check + transpose/split W_val, W_out into bf16 hi/lo
// ---------------------------------------------------------------------------
__global__ void __launch_bounds__(256) offcheck_kernel(const float* __restrict__ W_off)
{
    __shared__ int s[256];
    int t = threadIdx.x;
    int nz = 0;
    for (int i = t; i < 256 * 64; i += 256)
        nz |= (__float_as_int(W_off[i]) & 0x7fffffff);
    s[t] = nz;
    __syncthreads();
    for (int step = 128; step > 0; step >>= 1) {
        if (t < step) s[t] |= s[t + step];
        __syncthreads();
    }
    if (t == 0) g_off_nz = s[0];
}

__global__ void __launch_bounds__(256) prep_kernel(const float* __restrict__ Wv,
                                                   const float* __restrict__ Wo)
{
    int k = blockIdx.x;       // 0..255
    int n = threadIdx.x;      // 0..255
    {
        float v = Wv[k * 256 + n];
        __nv_bfloat16 h = __float2bfloat16_rn(v);
        g_Wt_hi[0][n * 256 + k] = h;
        g_Wt_lo[0][n * 256 + k] = __float2bfloat16_rn(v - __bfloat162float(h));
    }
    {
        float v = Wo[k * 256 + n];
        __nv_bfloat16 h = __float2bfloat16_rn(v);
        g_Wt_hi[1][n * 256 + k] = h;
        g_Wt_lo[1][n * 256 + k] = __float2bfloat16_rn(v - __bfloat162float(h));
    }
}

// ---------------------------------------------------------------------------
// mma.sync GEMM: C[M_TOTAL,256] = A[M_TOTAL,256] @ W[256,256] + bias
// CTA tile: M=128, N=64, K chunks of 64. 128 threads = 4 warps (2Mx2N),
// warp tile 64x32 (4x4 mma tiles of m16n8). 3-term bf16 split.
// MODE 0: A gathered from feats -> g_value.  MODE 1: A = g_mid -> Cout.
// ---------------------------------------------------------------------------
#define STRB  144                       // smem row stride in bytes (72 bf16)
#define SM_ROWPTR 0
#define SM_AHI 1024
#define SM_ALO (SM_AHI + 128 * STRB)    // +18432
#define SM_BHI (SM_ALO + 128 * STRB)
#define SM_BLO (SM_BHI + 64 * STRB)     // +9216
#define SMEM_TOTAL (SM_BLO + 64 * STRB)

template<int MODE>
__global__ void __launch_bounds__(128) gemm_mma(
    const float* __restrict__ f0, const float* __restrict__ f1,
    const float* __restrict__ f2, const float* __restrict__ f3,
    const float* __restrict__ bias, float* __restrict__ Cout)
{
    extern __shared__ char smem[];
    const int t = threadIdx.x;
    const int wid = t >> 5, lane = t & 31;
    const int m0 = blockIdx.x * 128;
    const int n0 = blockIdx.y * 64;

    const float** rowptr = (const float**)(smem + SM_ROWPTR);
    if (t < 128) {
        int r = m0 + t;
        const float* p;
        if (MODE == 0) {
            int b = r / LQ;
            int l = r - b * LQ;
            if (l < 16384)      p = f0 + ((size_t)b * 16384 + l) * 256;
            else if (l < 20480) p = f1 + ((size_t)b * 4096 + (l - 16384)) * 256;
            else if (l < 21504) p = f2 + ((size_t)b * 1024 + (l - 20480)) * 256;
            else                p = f3 + ((size_t)b * 256  + (l - 21504)) * 256;
        } else {
            p = g_mid + (size_t)r * 256;
        }
        rowptr[t] = p;
    }
    __syncthreads();

    const int wm = wid >> 1;            // 0..1 -> M offset wm*64
    const int wn = wid & 1;             // 0..1 -> N offset wn*32

    uint32_t sb = smem_to_u32(smem);
    const uint32_t sAhi = sb + SM_AHI, sAlo = sb + SM_ALO;
    const uint32_t sBhi = sb + SM_BHI, sBlo = sb + SM_BLO;

    // ldmatrix per-lane addressing
    const uint32_t a_row = wm * 64 + (lane & 15);
    const uint32_t a_koff = (lane >> 4) * 8;          // bf16 elems
    const uint32_t b_row = wn * 32 + (lane & 7);
    const uint32_t b_koff = ((lane >> 3) & 1) * 8;

    const __nv_bfloat16* WtH = g_Wt_hi[MODE];
    const __nv_bfloat16* WtL = g_Wt_lo[MODE];

    float acc[4][4][4];
    #pragma unroll
    for (int i = 0; i < 4; i++)
        #pragma unroll
        for (int j = 0; j < 4; j++)
            #pragma unroll
            for (int e = 0; e < 4; e++) acc[i][j][e] = 0.f;

    for (int c = 0; c < 4; c++) {
        // ---- load + split A chunk: 128 rows x 64 floats ----
        #pragma unroll
        for (int i = 0; i < 16; i++) {
            int idx = t + i * 128;                  // 2048 float4 slots
            int r = idx >> 4, c4 = (idx & 15) * 4;
            float4 v = *(const float4*)(rowptr[r] + c * 64 + c4);
            uint32_t h01 = bf2(v.x, v.y);
            uint32_t h23 = bf2(v.z, v.w);
            float hx = __uint_as_float(h01 << 16);
            float hy = __uint_as_float(h01 & 0xffff0000u);
            float hz = __uint_as_float(h23 << 16);
            float hw = __uint_as_float(h23 & 0xffff0000u);
            uint32_t l01 = bf2(v.x - hx, v.y - hy);
            uint32_t l23 = bf2(v.z - hz, v.w - hw);
            uint32_t off = r * STRB + c4 * 2;
            *(uint2*)(smem + SM_AHI + off) = make_uint2(h01, h23);
            *(uint2*)(smem + SM_ALO + off) = make_uint2(l01, l23);
        }
        // ---- load B chunk: 64 n-rows x 64 k (pre-split bf16) ----
        #pragma unroll
        for (int i = 0; i < 4; i++) {
            int idx = t + i * 128;                  // 512 uint4 slots
            int r = idx >> 3, c8 = (idx & 7) * 8;
            uint32_t off = r * STRB + c8 * 2;
            *(uint4*)(smem + SM_BHI + off) = *(const uint4*)(WtH + (size_t)(n0 + r) * 256 + c * 64 + c8);
            *(uint4*)(smem + SM_BLO + off) = *(const uint4*)(WtL + (size_t)(n0 + r) * 256 + c * 64 + c8);
        }
        __syncthreads();

        #pragma unroll
        for (int ks = 0; ks < 4; ks++) {
            const int k0 = ks * 16;
            uint32_t ahi[4][4], alo[4][4], bhi[4][2], blo[4][2];
            #pragma unroll
            for (int mt = 0; mt < 4; mt++) {
                uint32_t off = (a_row + mt * 16) * STRB + (k0 + a_koff) * 2;
                ldm_x4(sAhi + off, ahi[mt][0], ahi[mt][1], ahi[mt][2], ahi[mt][3]);
                ldm_x4(sAlo + off, alo[mt][0], alo[mt][1], alo[mt][2], alo[mt][3]);
            }
            #pragma unroll
            for (int nt = 0; nt < 4; nt++) {
                uint32_t off = (b_row + nt * 8) * STRB + (k0 + b_koff) * 2;
                ldm_x2(sBhi + off, bhi[nt][0], bhi[nt][1]);
                ldm_x2(sBlo + off, blo[nt][0], blo[nt][1]);
            }
            #pragma unroll
            for (int mt = 0; mt < 4; mt++)
                #pragma unroll
                for (int nt = 0; nt < 4; nt++) {
                    mma_bf16(acc[mt][nt], ahi[mt], bhi[nt]);
                    mma_bf16(acc[mt][nt], ahi[mt], blo[nt]);
                    mma_bf16(acc[mt][nt], alo[mt], bhi[nt]);
                }
        }
        __syncthreads();
    }

    // ---- epilogue ----
    float* C = (MODE == 0) ? g_value : Cout;
    const int row_base = m0 + wm * 64;
    const int col_base = n0 + wn * 32;
    #pragma unroll
    for (int nt = 0; nt < 4; nt++) {
        const int col = col_base + nt * 8 + (lane & 3) * 2;
        float2 bv = *(const float2*)(bias + col);
        #pragma unroll
        for (int mt = 0; mt < 4; mt++) {
            int r0 = row_base + mt * 16 + (lane >> 2);
            float2 o0, o1;
            o0.x = acc[mt][nt][0] + bv.x; o0.y = acc[mt][nt][1] + bv.y;
            o1.x = acc[mt][nt][2] + bv.x; o1.y = acc[mt][nt][3] + bv.y;
            *(float2*)(C + (size_t)r0 * 256 + col)       = o0;
            *(float2*)(C + (size_t)(r0 + 8) * 256 + col) = o1;
        }
    }
}

// ----------------------------------------------------------------------------
// Sampling kernel (unchanged)
// ----------------------------------------------------------------------------
__global__ void __launch_bounds__(256) sample_kernel(
    const float* __restrict__ query,
    const float* __restrict__ refpts,
    const float* __restrict__ W_off, const float* __restrict__ b_off,
    const float* __restrict__ W_attn, const float* __restrict__ b_attn)
{
    __shared__ float Qs[16][256];
    __shared__ float Ws[32][64];
    __shared__ float logit[16][96];
    __shared__ float attn_s[16][8][4];
    __shared__ int   vrow[16][8][4][4];
    __shared__ float refs[16][4][2];

    const int t = threadIdx.x;
    const long long gq0 = (long long)blockIdx.x * 16;

    {
        const float4* src = (const float4*)(query + gq0 * 256);
        float4* dst = (float4*)&Qs[0][0];
        #pragma unroll
        for (int i = 0; i < 4; i++) dst[t + i * 256] = src[t + i * 256];
    }
    if (t < 128) ((float*)refs)[t] = refpts[gq0 * 8 + t];
    __syncthreads();

    const int row = t >> 4;
    const int cx  = t & 15;

    {
        float a0 = 0.f, a1 = 0.f;
        float* WsA = &Ws[0][0];
        for (int k0 = 0; k0 < 256; k0 += 32) {
            #pragma unroll
            for (int i = 0; i < 4; i++) {
                int idx = t + i * 256;
                WsA[idx] = W_attn[(size_t)(k0 + (idx >> 5)) * 32 + (idx & 31)];
            }
            __syncthreads();
            #pragma unroll
            for (int kk = 0; kk < 32; kk++) {
                float q = Qs[row][k0 + kk];
                a0 += q * WsA[kk * 32 + cx];
                a1 += q * WsA[kk * 32 + cx + 16];
            }
            __syncthreads();
        }
        logit[row][64 + cx]      = a0 + b_attn[cx];
        logit[row][64 + cx + 16] = a1 + b_attn[cx + 16];
    }

    if (g_off_nz) {
        float a[4] = {0.f, 0.f, 0.f, 0.f};
        const int co = cx * 4;
        for (int k0 = 0; k0 < 256; k0 += 32) {
            #pragma unroll
            for (int i = 0; i < 2; i++) {
                int fi = t + i * 256;
                int kk = fi >> 4, c = (fi & 15) * 4;
                *(float4*)&Ws[kk][c] = *(const float4*)(W_off + (size_t)(k0 + kk) * 64 + c);
            }
            __syncthreads();
            #pragma unroll
            for (int kk = 0; kk < 32; kk++) {
                float q = Qs[row][k0 + kk];
                #pragma unroll
                for (int j = 0; j < 4; j++) a[j] += q * Ws[kk][co + j];
            }
            __syncthreads();
        }
        #pragma unroll
        for (int j = 0; j < 4; j++) logit[row][co + j] = a[j] + b_off[co + j];
    } else {
        #pragma unroll
        for (int i = 0; i < 4; i++) {
            int idx = t + i * 256;
            logit[idx >> 6][idx & 63] = b_off[idx & 63];
        }
    }
    __syncthreads();

    if (t < 128) {
        const int r = t >> 3, h = t & 7;
        const long long gq = gq0 + r;
        const int b = (int)(gq / LQ);

        float l[4];
        float mx = -1e30f;
        #pragma unroll
        for (int p = 0; p < 4; p++) { l[p] = logit[r][64 + h * 4 + p]; mx = fmaxf(mx, l[p]); }
        float s = 0.f;
        #pragma unroll
        for (int p = 0; p < 4; p++) { l[p] = expf(l[p] - mx); s += l[p]; }
        float inv = 1.0f / s;
        #pragma unroll
        for (int p = 0; p < 4; p++) attn_s[r][h][p] = l[p] * inv;

        const int DIMS[4]  = {128, 64, 32, 16};
        const int START[4] = {0, 16384, 20480, 21504};
        #pragma unroll
        for (int lvl = 0; lvl < 4; lvl++) {
            float rx = refs[r][lvl][0];
            float ry = refs[r][lvl][1];
            int Wl = DIMS[lvl];
            #pragma unroll
            for (int p = 0; p < 4; p++) {
                float ox = logit[r][h * 8 + p * 2 + 0];
                float oy = logit[r][h * 8 + p * 2 + 1];
                float sx = fminf(fmaxf(rx + ox, 0.f), 1.f);
                float sy = fminf(fmaxf(ry + oy, 0.f), 1.f);
                int x0 = (int)floorf(sx * (float)(Wl - 1));
                int y0 = (int)floorf(sy * (float)(Wl - 1));
                vrow[r][h][p][lvl] = b * LQ + START[lvl] + y0 * Wl + x0;
            }
        }
    }
    __syncthreads();

    {
        const int h = t >> 5;
        const int c = t & 31;
        const int coff = h * 32 + c;
        for (int r = 0; r < 16; r++) {
            float v[16];
            #pragma unroll
            for (int p = 0; p < 4; p++)
                #pragma unroll
                for (int lvl = 0; lvl < 4; lvl++)
                    v[p * 4 + lvl] = g_value[(size_t)vrow[r][h][p][lvl] * 256 + coff];
            float a = 0.f;
            #pragma unroll
            for (int p = 0; p < 4; p++) {
                float w = attn_s[r][h][p];
                #pragma unroll
                for (int lvl = 0; lvl < 4; lvl++) a += w * v[p * 4 + lvl];
            }
            g_mid[(size_t)(gq0 + r) * 256 + coff] = a;
        }
    }
}

// ----------------------------------------------------------------------------
extern "C" void kernel_launch(void* const* d_in, const int* in_sizes, int n_in,
                              void* d_out, int out_size)
{
    (void)in_sizes; (void)n_in; (void)out_size;
    const float* query  = (const float*)d_in[0];
    const float* refpts = (const float*)d_in[1];
    const float* f0     = (const float*)d_in[2];
    const float* f1     = (const float*)d_in[3];
    const float* f2     = (const float*)d_in[4];
    const float* f3     = (const float*)d_in[5];
    const float* W_off  = (const float*)d_in[6];
    const float* b_off  = (const float*)d_in[7];
    const float* W_attn = (const float*)d_in[8];
    const float* b_attn = (const float*)d_in[9];
    const float* W_val  = (const float*)d_in[10];
    const float* b_val  = (const float*)d_in[11];
    const float* W_out  = (const float*)d_in[12];
    const float* b_out  = (const float*)d_in[13];
    float* out = (float*)d_out;

    cudaFuncSetAttribute(gemm_mma<0>, cudaFuncAttributeMaxDynamicSharedMemorySize, SMEM_TOTAL);
    cudaFuncSetAttribute(gemm_mma<1>, cudaFuncAttributeMaxDynamicSharedMemorySize, SMEM_TOTAL);

    offcheck_kernel<<<1, 256>>>(W_off);
    prep_kernel<<<256, 256>>>(W_val, W_out);

    dim3 ggrid(M_TOTAL / 128, 4);
    gemm_mma<0><<<ggrid, 128, SMEM_TOTAL>>>(f0, f1, f2, f3, b_val, nullptr);
    sample_kernel<<<M_TOTAL / 16, 256>>>(query, refpts, W_off, b_off, W_attn, b_attn);
    gemm_mma<1><<<ggrid, 128, SMEM_TOTAL>>>(nullptr, nullptr, nullptr, nullptr, b_out, out);
}

// round 5
// speedup vs baseline: 2.0184x; 1.3683x over previous
#include <cuda_runtime.h>
#include <cuda_bf16.h>
#include <cstdint>
#include <cstddef>

// ============================================================================
// DeformableAttention: B=4, Lq=21760, DIM=256, NH=8, NP=4, HD=32
// Levels: (128,128),(64,64),(32,32),(16,16) -> Lv = 21760, starts 0/16384/20480/21504
// M = B*Lq = B*Lv = 87040
// All three projections (value, logits, output) on mma.sync bf16 3-term split.
// ============================================================================

#define M_TOTAL 87040
#define LQ 21760

__device__ float          g_value[(size_t)M_TOTAL * 256];
__device__ float          g_logit[(size_t)M_TOTAL * 128];   // cols 0-63 off, 64-95 attn
__device__ __nv_bfloat16  g_mid_hi[(size_t)M_TOTAL * 256];
__device__ __nv_bfloat16  g_mid_lo[(size_t)M_TOTAL * 256];
// pre-transposed, hi/lo split weights [slot][n*256+k]: 0=W_val, 1=W_out, 2=cat(W_off|W_attn|0)
__device__ __nv_bfloat16  g_Wt_hi[3][256 * 256];
__device__ __nv_bfloat16  g_Wt_lo[3][256 * 256];
__device__ float          g_bcat[128];

// ---------------------------------------------------------------------------
__device__ __forceinline__ uint32_t smem_to_u32(const void* p) {
    uint32_t a;
    asm("{ .reg .u64 t; cvta.to.shared.u64 t, %1; cvt.u32.u64 %0, t; }" : "=r"(a) : "l"(p));
    return a;
}
__device__ __forceinline__ uint32_t bf2(float x, float y) {   // lo=x, hi=y
    uint32_t r;
    asm("cvt.rn.bf16x2.f32 %0, %1, %2;" : "=r"(r) : "f"(y), "f"(x));
    return r;
}
__device__ __forceinline__ void ldm_x4(uint32_t addr, uint32_t& r0, uint32_t& r1,
                                       uint32_t& r2, uint32_t& r3) {
    asm volatile("ldmatrix.sync.aligned.m8n8.x4.shared.b16 {%0,%1,%2,%3}, [%4];"
                 : "=r"(r0), "=r"(r1), "=r"(r2), "=r"(r3) : "r"(addr));
}
__device__ __forceinline__ void ldm_x2(uint32_t addr, uint32_t& r0, uint32_t& r1) {
    asm volatile("ldmatrix.sync.aligned.m8n8.x2.shared.b16 {%0,%1}, [%2];"
                 : "=r"(r0), "=r"(r1) : "r"(addr));
}
__device__ __forceinline__ void mma_bf16(float* d, const uint32_t* a, const uint32_t* b) {
    asm volatile("mma.sync.aligned.m16n8k16.row.col.f32.bf16.bf16.f32 "
                 "{%0,%1,%2,%3}, {%4,%5,%6,%7}, {%8,%9}, {%0,%1,%2,%3};"
                 : "+f"(d[0]), "+f"(d[1]), "+f"(d[2]), "+f"(d[3])
                 : "r"(a[0]), "r"(a[1]), "r"(a[2]), "r"(a[3]), "r"(b[0]), "r"(b[1]));
}

// ---------------------------------------------------------------------------
// prep: transpose + hi/lo split all weights; build concatenated bias
// ---------------------------------------------------------------------------
__global__ void __launch_bounds__(256) prep_kernel(
    const float* __restrict__ Wv, const float* __restrict__ Wo,
    const float* __restrict__ Woff, const float* __restrict__ Wattn,
    const float* __restrict__ boff, const float* __restrict__ battn)
{
    int k = blockIdx.x;       // 0..255
    int n = threadIdx.x;      // 0..255
    {
        float v = Wv[k * 256 + n];
        __nv_bfloat16 h = __float2bfloat16_rn(v);
        g_Wt_hi[0][n * 256 + k] = h;
        g_Wt_lo[0][n * 256 + k] = __float2bfloat16_rn(v - __bfloat162float(h));
    }
    {
        float v = Wo[k * 256 + n];
        __nv_bfloat16 h = __float2bfloat16_rn(v);
        g_Wt_hi[1][n * 256 + k] = h;
        g_Wt_lo[1][n * 256 + k] = __float2bfloat16_rn(v - __bfloat162float(h));
    }
    if (n < 128) {
        float v = 0.f;
        if (n < 64)      v = Woff[k * 64 + n];
        else if (n < 96) v = Wattn[k * 32 + (n - 64)];
        __nv_bfloat16 h = __float2bfloat16_rn(v);
        g_Wt_hi[2][n * 256 + k] = h;
        g_Wt_lo[2][n * 256 + k] = __float2bfloat16_rn(v - __bfloat162float(h));
        if (k == 0) {
            float bb = 0.f;
            if (n < 64)      bb = boff[n];
            else if (n < 96) bb = battn[n - 64];
            g_bcat[n] = bb;
        }
    }
}

// ---------------------------------------------------------------------------
// Unified mma.sync GEMM: C = A[.,256] @ W[256, N] + bias
// CTA tile: M=64, N=128 (grid.y covers N=256 for modes 0/1). K chunks of 64.
// 256 threads = 8 warps, warp tile 64x16 (4 m-tiles x 2 n-tiles).
// MODE 0: A = feats gather (fp32->split)   -> g_value    [N=256]
// MODE 1: A = g_mid_hi/lo (pre-split copy) -> Cout       [N=256]
// MODE 2: A = query (fp32->split)          -> g_logit    [N=128]
// ---------------------------------------------------------------------------
#define STRB 144
#define SM_ROWPTR 0
#define SM_AHI 512
#define SM_ALO (SM_AHI + 64 * STRB)
#define SM_BHI (SM_ALO + 64 * STRB)
#define SM_BLO (SM_BHI + 128 * STRB)
#define SMEM_TOTAL (SM_BLO + 128 * STRB)   // 55808 B

template<int MODE>
__global__ void __launch_bounds__(256, 2) gemm_mma(
    const float* __restrict__ f0, const float* __restrict__ f1,
    const float* __restrict__ f2, const float* __restrict__ f3,
    const float* __restrict__ bias, float* __restrict__ Cout)
{
    extern __shared__ char smem[];
    const int t = threadIdx.x;
    const int wid = t >> 5, lane = t & 31;
    const int m0 = blockIdx.x * 64;
    const int n0 = blockIdx.y * 128;

    const float** rowptr = (const float**)(smem + SM_ROWPTR);
    if (MODE != 1 && t < 64) {
        int r = m0 + t;
        const float* p;
        if (MODE == 0) {
            int b = r / LQ;
            int l = r - b * LQ;
            if (l < 16384)      p = f0 + ((size_t)b * 16384 + l) * 256;
            else if (l < 20480) p = f1 + ((size_t)b * 4096 + (l - 16384)) * 256;
            else if (l < 21504) p = f2 + ((size_t)b * 1024 + (l - 20480)) * 256;
            else                p = f3 + ((size_t)b * 256  + (l - 21504)) * 256;
        } else {
            p = f0 + (size_t)r * 256;   // query
        }
        rowptr[t] = p;
    }
    if (MODE != 1) __syncthreads();

    const int slot = (MODE == 0) ? 0 : (MODE == 1) ? 1 : 2;
    const __nv_bfloat16* WtH = g_Wt_hi[slot];
    const __nv_bfloat16* WtL = g_Wt_lo[slot];

    uint32_t sb = smem_to_u32(smem);
    const uint32_t sAhi = sb + SM_AHI, sAlo = sb + SM_ALO;
    const uint32_t sBhi = sb + SM_BHI, sBlo = sb + SM_BLO;

    const uint32_t a_row = lane & 15;
    const uint32_t a_koff = (lane >> 4) * 8;
    const uint32_t b_row = wid * 16 + (lane & 7);
    const uint32_t b_koff = ((lane >> 3) & 1) * 8;

    float acc[4][2][4];
    #pragma unroll
    for (int i = 0; i < 4; i++)
        #pragma unroll
        for (int j = 0; j < 2; j++)
            #pragma unroll
            for (int e = 0; e < 4; e++) acc[i][j][e] = 0.f;

    for (int c = 0; c < 4; c++) {
        // ---- A chunk: 64 rows x 64 k ----
        if (MODE == 1) {
            #pragma unroll
            for (int i = 0; i < 2; i++) {
                int idx = t + i * 256;                // 512 uint4 slots
                int r = idx >> 3, c8 = (idx & 7) * 8;
                size_t gofs = (size_t)(m0 + r) * 256 + c * 64 + c8;
                uint32_t off = r * STRB + c8 * 2;
                *(uint4*)(smem + SM_AHI + off) = *(const uint4*)(g_mid_hi + gofs);
                *(uint4*)(smem + SM_ALO + off) = *(const uint4*)(g_mid_lo + gofs);
            }
        } else {
            #pragma unroll
            for (int i = 0; i < 4; i++) {
                int idx = t + i * 256;                // 1024 float4 slots
                int r = idx >> 4, c4 = (idx & 15) * 4;
                float4 v = *(const float4*)(rowptr[r] + c * 64 + c4);
                uint32_t h01 = bf2(v.x, v.y);
                uint32_t h23 = bf2(v.z, v.w);
                float hx = __uint_as_float(h01 << 16);
                float hy = __uint_as_float(h01 & 0xffff0000u);
                float hz = __uint_as_float(h23 << 16);
                float hw = __uint_as_float(h23 & 0xffff0000u);
                uint32_t l01 = bf2(v.x - hx, v.y - hy);
                uint32_t l23 = bf2(v.z - hz, v.w - hw);
                uint32_t off = r * STRB + c4 * 2;
                *(uint2*)(smem + SM_AHI + off) = make_uint2(h01, h23);
                *(uint2*)(smem + SM_ALO + off) = make_uint2(l01, l23);
            }
        }
        // ---- B chunk: 128 n-rows x 64 k ----
        #pragma unroll
        for (int i = 0; i < 4; i++) {
            int idx = t + i * 256;                    // 1024 uint4 slots
            int r = idx >> 3, c8 = (idx & 7) * 8;
            size_t gofs = (size_t)(n0 + r) * 256 + c * 64 + c8;
            uint32_t off = r * STRB + c8 * 2;
            *(uint4*)(smem + SM_BHI + off) = *(const uint4*)(WtH + gofs);
            *(uint4*)(smem + SM_BLO + off) = *(const uint4*)(WtL + gofs);
        }
        __syncthreads();

        #pragma unroll
        for (int ks = 0; ks < 4; ks++) {
            const int k0 = ks * 16;
            uint32_t ahi[4][4], alo[4][4], bhi[2][2], blo[2][2];
            #pragma unroll
            for (int mt = 0; mt < 4; mt++) {
                uint32_t off = (a_row + mt * 16) * STRB + (k0 + a_koff) * 2;
                ldm_x4(sAhi + off, ahi[mt][0], ahi[mt][1], ahi[mt][2], ahi[mt][3]);
                ldm_x4(sAlo + off, alo[mt][0], alo[mt][1], alo[mt][2], alo[mt][3]);
            }
            #pragma unroll
            for (int nt = 0; nt < 2; nt++) {
                uint32_t off = (b_row + nt * 8) * STRB + (k0 + b_koff) * 2;
                ldm_x2(sBhi + off, bhi[nt][0], bhi[nt][1]);
                ldm_x2(sBlo + off, blo[nt][0], blo[nt][1]);
            }
            #pragma unroll
            for (int mt = 0; mt < 4; mt++)
                #pragma unroll
                for (int nt = 0; nt < 2; nt++) {
                    mma_bf16(acc[mt][nt], ahi[mt], bhi[nt]);
                    mma_bf16(acc[mt][nt], ahi[mt], blo[nt]);
                    mma_bf16(acc[mt][nt], alo[mt], bhi[nt]);
                }
        }
        __syncthreads();
    }

    // ---- epilogue ----
    float* C;
    int ldc;
    const float* bs;
    if (MODE == 0)      { C = g_value; ldc = 256; bs = bias; }
    else if (MODE == 1) { C = Cout;    ldc = 256; bs = bias; }
    else                { C = g_logit; ldc = 128; bs = g_bcat; }

    const int col_base = n0 + wid * 16;
    #pragma unroll
    for (int nt = 0; nt < 2; nt++) {
        const int col = col_base + nt * 8 + (lane & 3) * 2;
        float2 bv = *(const float2*)(bs + (col - (MODE == 2 ? 0 : 0)) - (MODE == 2 ? n0 : 0));
        // (MODE==2: n0==0 so col indexes g_bcat directly)
        #pragma unroll
        for (int mt = 0; mt < 4; mt++) {
            int r0 = m0 + mt * 16 + (lane >> 2);
            float2 o0, o1;
            o0.x = acc[mt][nt][0] + bv.x; o0.y = acc[mt][nt][1] + bv.y;
            o1.x = acc[mt][nt][2] + bv.x; o1.y = acc[mt][nt][3] + bv.y;
            *(float2*)(C + (size_t)r0 * ldc + col)       = o0;
            *(float2*)(C + (size_t)(r0 + 8) * ldc + col) = o1;
        }
    }
}

// ----------------------------------------------------------------------------
// Sample kernel: softmax + nearest index + gather. 32 queries / block.
// Reads g_logit (bias already applied), writes g_mid_hi/lo (bf16 split).
// ----------------------------------------------------------------------------
__global__ void __launch_bounds__(256) sample_kernel(const float* __restrict__ refpts)
{
    __shared__ float logit[32][96];       // 12 KB
    __shared__ float attn_s[32][8][4];    // 4 KB
    __shared__ int   vrow[32][8][16];     // 16 KB
    __shared__ float refs[32][4][2];      // 1 KB

    const int t = threadIdx.x;
    const long long gq0 = (long long)blockIdx.x * 32;

    // ---- load logits (32 rows x 96 cols) ----
    #pragma unroll
    for (int i = 0; i < 3; i++) {
        int idx = t + i * 256;            // 768 float4 slots
        int r = idx / 24, cq = (idx % 24) * 4;
        *(float4*)&logit[r][cq] = *(const float4*)(g_logit + (gq0 + r) * 128 + cq);
    }
    ((float*)refs)[t] = refpts[gq0 * 8 + t];
    __syncthreads();

    // ---- softmax + indices: one thread per (row, head) ----
    {
        const int r = t >> 3, h = t & 7;
        const long long gq = gq0 + r;
        const int b = (int)(gq / LQ);

        float l[4];
        float mx = -1e30f;
        #pragma unroll
        for (int p = 0; p < 4; p++) { l[p] = logit[r][64 + h * 4 + p]; mx = fmaxf(mx, l[p]); }
        float s = 0.f;
        #pragma unroll
        for (int p = 0; p < 4; p++) { l[p] = expf(l[p] - mx); s += l[p]; }
        float inv = 1.0f / s;
        #pragma unroll
        for (int p = 0; p < 4; p++) attn_s[r][h][p] = l[p] * inv;

        const int DIMS[4]  = {128, 64, 32, 16};
        const int START[4] = {0, 16384, 20480, 21504};
        #pragma unroll
        for (int lvl = 0; lvl < 4; lvl++) {
            float rx = refs[r][lvl][0];
            float ry = refs[r][lvl][1];
            int Wl = DIMS[lvl];
            #pragma unroll
            for (int p = 0; p < 4; p++) {
                float ox = logit[r][h * 8 + p * 2 + 0];
                float oy = logit[r][h * 8 + p * 2 + 1];
                float sx = fminf(fmaxf(rx + ox, 0.f), 1.f);
                float sy = fminf(fmaxf(ry + oy, 0.f), 1.f);
                int x0 = (int)floorf(sx * (float)(Wl - 1));
                int y0 = (int)floorf(sy * (float)(Wl - 1));
                vrow[r][h][p * 4 + lvl] = b * LQ + START[lvl] + y0 * Wl + x0;
            }
        }
    }
    __syncthreads();

    // ---- gather: warp w -> rows 4w..4w+3; lane = channel within head ----
    {
        const int w = t >> 5, lane = t & 31;
        #pragma unroll
        for (int rw = 0; rw < 4; rw++) {
            const int r = w * 4 + rw;
            #pragma unroll
            for (int h = 0; h < 8; h++) {
                const int coff = h * 32 + lane;
                const int* vr = vrow[r][h];
                float v[16];
                #pragma unroll
                for (int s = 0; s < 16; s++)
                    v[s] = g_value[(size_t)vr[s] * 256 + coff];
                float a = 0.f;
                #pragma unroll
                for (int p = 0; p < 4; p++) {
                    float wgt = attn_s[r][h][p];
                    #pragma unroll
                    for (int lvl = 0; lvl < 4; lvl++) a += wgt * v[p * 4 + lvl];
                }
                __nv_bfloat16 hi = __float2bfloat16_rn(a);
                __nv_bfloat16 lo = __float2bfloat16_rn(a - __bfloat162float(hi));
                size_t o = (size_t)(gq0 + r) * 256 + coff;
                g_mid_hi[o] = hi;
                g_mid_lo[o] = lo;
            }
        }
    }
}

// ----------------------------------------------------------------------------
extern "C" void kernel_launch(void* const* d_in, const int* in_sizes, int n_in,
                              void* d_out, int out_size)
{
    (void)in_sizes; (void)n_in; (void)out_size;
    const float* query  = (const float*)d_in[0];
    const float* refpts = (const float*)d_in[1];
    const float* f0     = (const float*)d_in[2];
    const float* f1     = (const float*)d_in[3];
    const float* f2     = (const float*)d_in[4];
    const float* f3     = (const float*)d_in[5];
    const float* W_off  = (const float*)d_in[6];
    const float* b_off  = (const float*)d_in[7];
    const float* W_attn = (const float*)d_in[8];
    const float* b_attn = (const float*)d_in[9];
    const float* W_val  = (const float*)d_in[10];
    const float* b_val  = (const float*)d_in[11];
    const float* W_out  = (const float*)d_in[12];
    const float* b_out  = (const float*)d_in[13];
    float* out = (float*)d_out;

    cudaFuncSetAttribute(gemm_mma<0>, cudaFuncAttributeMaxDynamicSharedMemorySize, SMEM_TOTAL);
    cudaFuncSetAttribute(gemm_mma<1>, cudaFuncAttributeMaxDynamicSharedMemorySize, SMEM_TOTAL);
    cudaFuncSetAttribute(gemm_mma<2>, cudaFuncAttributeMaxDynamicSharedMemorySize, SMEM_TOTAL);

    prep_kernel<<<256, 256>>>(W_val, W_out, W_off, W_attn, b_off, b_attn);

    dim3 g2(M_TOTAL / 64, 2);
    dim3 g1(M_TOTAL / 64, 1);
    // logits GEMM (query @ [W_off|W_attn|0]) -> g_logit
    gemm_mma<2><<<g1, 256, SMEM_TOTAL>>>(query, nullptr, nullptr, nullptr, nullptr, nullptr);
    // value projection -> g_value
    gemm_mma<0><<<g2, 256, SMEM_TOTAL>>>(f0, f1, f2, f3, b_val, nullptr);
    // softmax + gather -> g_mid (bf16 split)
    sample_kernel<<<M_TOTAL / 32, 256>>>(refpts);
    // output projection -> out
    gemm_mma<1><<<g2, 256, SMEM_TOTAL>>>(nullptr, nullptr, nullptr, nullptr, b_out, out);
}

// round 7
// speedup vs baseline: 2.1215x; 1.0511x over previous
#include <cuda_runtime.h>
#include <cuda_bf16.h>
#include <cstdint>
#include <cstddef>

// ============================================================================
// DeformableAttention: B=4, Lq=21760, DIM=256, NH=8, NP=4, HD=32
// Levels: (128,128),(64,64),(32,32),(16,16) -> Lv = 21760, starts 0/16384/20480/21504
// M = B*Lq = B*Lv = 87040
// All three projections (value, logits, output) on mma.sync bf16 3-term split.
// ============================================================================

#define M_TOTAL 87040
#define LQ 21760

__device__ float          g_value[(size_t)M_TOTAL * 256];
__device__ float          g_logit[(size_t)M_TOTAL * 128];   // cols 0-63 off, 64-95 attn
__device__ __nv_bfloat16  g_mid_hi[(size_t)M_TOTAL * 256];
__device__ __nv_bfloat16  g_mid_lo[(size_t)M_TOTAL * 256];
// pre-transposed, hi/lo split weights [slot][n*256+k]: 0=W_val, 1=W_out, 2=cat(W_off|W_attn|0)
__device__ __nv_bfloat16  g_Wt_hi[3][256 * 256];
__device__ __nv_bfloat16  g_Wt_lo[3][256 * 256];
__device__ float          g_bcat[128];

// ---------------------------------------------------------------------------
__device__ __forceinline__ uint32_t smem_to_u32(const void* p) {
    uint32_t a;
    asm("{ .reg .u64 t; cvta.to.shared.u64 t, %1; cvt.u32.u64 %0, t; }" : "=r"(a) : "l"(p));
    return a;
}
__device__ __forceinline__ uint32_t bf2(float x, float y) {   // lo=x, hi=y
    uint32_t r;
    asm("cvt.rn.bf16x2.f32 %0, %1, %2;" : "=r"(r) : "f"(y), "f"(x));
    return r;
}
__device__ __forceinline__ void ldm_x4(uint32_t addr, uint32_t& r0, uint32_t& r1,
                                       uint32_t& r2, uint32_t& r3) {
    asm volatile("ldmatrix.sync.aligned.m8n8.x4.shared.b16 {%0,%1,%2,%3}, [%4];"
                 : "=r"(r0), "=r"(r1), "=r"(r2), "=r"(r3) : "r"(addr));
}
__device__ __forceinline__ void ldm_x2(uint32_t addr, uint32_t& r0, uint32_t& r1) {
    asm volatile("ldmatrix.sync.aligned.m8n8.x2.shared.b16 {%0,%1}, [%2];"
                 : "=r"(r0), "=r"(r1) : "r"(addr));
}
__device__ __forceinline__ void mma_bf16(float* d, const uint32_t* a, const uint32_t* b) {
    asm volatile("mma.sync.aligned.m16n8k16.row.col.f32.bf16.bf16.f32 "
                 "{%0,%1,%2,%3}, {%4,%5,%6,%7}, {%8,%9}, {%0,%1,%2,%3};"
                 : "+f"(d[0]), "+f"(d[1]), "+f"(d[2]), "+f"(d[3])
                 : "r"(a[0]), "r"(a[1]), "r"(a[2]), "r"(a[3]), "r"(b[0]), "r"(b[1]));
}

// ---------------------------------------------------------------------------
// prep: transpose + hi/lo split all weights; build concatenated bias
// ---------------------------------------------------------------------------
__global__ void __launch_bounds__(256) prep_kernel(
    const float* __restrict__ Wv, const float* __restrict__ Wo,
    const float* __restrict__ Woff, const float* __restrict__ Wattn,
    const float* __restrict__ boff, const float* __restrict__ battn)
{
    int k = blockIdx.x;       // 0..255
    int n = threadIdx.x;      // 0..255
    {
        float v = Wv[k * 256 + n];
        __nv_bfloat16 h = __float2bfloat16_rn(v);
        g_Wt_hi[0][n * 256 + k] = h;
        g_Wt_lo[0][n * 256 + k] = __float2bfloat16_rn(v - __bfloat162float(h));
    }
    {
        float v = Wo[k * 256 + n];
        __nv_bfloat16 h = __float2bfloat16_rn(v);
        g_Wt_hi[1][n * 256 + k] = h;
        g_Wt_lo[1][n * 256 + k] = __float2bfloat16_rn(v - __bfloat162float(h));
    }
    if (n < 128) {
        float v = 0.f;
        if (n < 64)      v = Woff[k * 64 + n];
        else if (n < 96) v = Wattn[k * 32 + (n - 64)];
        __nv_bfloat16 h = __float2bfloat16_rn(v);
        g_Wt_hi[2][n * 256 + k] = h;
        g_Wt_lo[2][n * 256 + k] = __float2bfloat16_rn(v - __bfloat162float(h));
        if (k == 0) {
            float bb = 0.f;
            if (n < 64)      bb = boff[n];
            else if (n < 96) bb = battn[n - 64];
            g_bcat[n] = bb;
        }
    }
}

// ---------------------------------------------------------------------------
// Unified mma.sync GEMM: C = A[.,256] @ W[256, N] + bias
// CTA tile: M=64, N=128 (grid.y covers N=256 for modes 0/1). K chunks of 64.
// 256 threads = 8 warps, warp tile 64x16 (4 m-tiles x 2 n-tiles).
// MODE 0: A = feats gather (fp32->split)   -> g_value    [N=256]
// MODE 1: A = g_mid_hi/lo (pre-split copy) -> Cout       [N=256]
// MODE 2: A = query (fp32->split)          -> g_logit    [N=128]
// ---------------------------------------------------------------------------
#define STRB 144
#define SM_ROWPTR 0
#define SM_AHI 512
#define SM_ALO (SM_AHI + 64 * STRB)
#define SM_BHI (SM_ALO + 64 * STRB)
#define SM_BLO (SM_BHI + 128 * STRB)
#define SMEM_TOTAL (SM_BLO + 128 * STRB)   // 55808 B

template<int MODE>
__global__ void __launch_bounds__(256, 2) gemm_mma(
    const float* __restrict__ f0, const float* __restrict__ f1,
    const float* __restrict__ f2, const float* __restrict__ f3,
    const float* __restrict__ bias, float* __restrict__ Cout)
{
    extern __shared__ char smem[];
    const int t = threadIdx.x;
    const int wid = t >> 5, lane = t & 31;
    const int m0 = blockIdx.x * 64;
    const int n0 = blockIdx.y * 128;

    const float** rowptr = (const float**)(smem + SM_ROWPTR);
    if (MODE != 1 && t < 64) {
        int r = m0 + t;
        const float* p;
        if (MODE == 0) {
            int b = r / LQ;
            int l = r - b * LQ;
            if (l < 16384)      p = f0 + ((size_t)b * 16384 + l) * 256;
            else if (l < 20480) p = f1 + ((size_t)b * 4096 + (l - 16384)) * 256;
            else if (l < 21504) p = f2 + ((size_t)b * 1024 + (l - 20480)) * 256;
            else                p = f3 + ((size_t)b * 256  + (l - 21504)) * 256;
        } else {
            p = f0 + (size_t)r * 256;   // query
        }
        rowptr[t] = p;
    }
    if (MODE != 1) __syncthreads();

    const int slot = (MODE == 0) ? 0 : (MODE == 1) ? 1 : 2;
    const __nv_bfloat16* WtH = g_Wt_hi[slot];
    const __nv_bfloat16* WtL = g_Wt_lo[slot];

    uint32_t sb = smem_to_u32(smem);
    const uint32_t sAhi = sb + SM_AHI, sAlo = sb + SM_ALO;
    const uint32_t sBhi = sb + SM_BHI, sBlo = sb + SM_BLO;

    const uint32_t a_row = lane & 15;
    const uint32_t a_koff = (lane >> 4) * 8;
    const uint32_t b_row = wid * 16 + (lane & 7);
    const uint32_t b_koff = ((lane >> 3) & 1) * 8;

    float acc[4][2][4];
    #pragma unroll
    for (int i = 0; i < 4; i++)
        #pragma unroll
        for (int j = 0; j < 2; j++)
            #pragma unroll
            for (int e = 0; e < 4; e++) acc[i][j][e] = 0.f;

    for (int c = 0; c < 4; c++) {
        // ---- A chunk: 64 rows x 64 k ----
        if (MODE == 1) {
            #pragma unroll
            for (int i = 0; i < 2; i++) {
                int idx = t + i * 256;                // 512 uint4 slots
                int r = idx >> 3, c8 = (idx & 7) * 8;
                size_t gofs = (size_t)(m0 + r) * 256 + c * 64 + c8;
                uint32_t off = r * STRB + c8 * 2;
                *(uint4*)(smem + SM_AHI + off) = *(const uint4*)(g_mid_hi + gofs);
                *(uint4*)(smem + SM_ALO + off) = *(const uint4*)(g_mid_lo + gofs);
            }
        } else {
            #pragma unroll
            for (int i = 0; i < 4; i++) {
                int idx = t + i * 256;                // 1024 float4 slots
                int r = idx >> 4, c4 = (idx & 15) * 4;
                float4 v = *(const float4*)(rowptr[r] + c * 64 + c4);
                uint32_t h01 = bf2(v.x, v.y);
                uint32_t h23 = bf2(v.z, v.w);
                float hx = __uint_as_float(h01 << 16);
                float hy = __uint_as_float(h01 & 0xffff0000u);
                float hz = __uint_as_float(h23 << 16);
                float hw = __uint_as_float(h23 & 0xffff0000u);
                uint32_t l01 = bf2(v.x - hx, v.y - hy);
                uint32_t l23 = bf2(v.z - hz, v.w - hw);
                uint32_t off = r * STRB + c4 * 2;
                *(uint2*)(smem + SM_AHI + off) = make_uint2(h01, h23);
                *(uint2*)(smem + SM_ALO + off) = make_uint2(l01, l23);
            }
        }
        // ---- B chunk: 128 n-rows x 64 k ----
        #pragma unroll
        for (int i = 0; i < 4; i++) {
            int idx = t + i * 256;                    // 1024 uint4 slots
            int r = idx >> 3, c8 = (idx & 7) * 8;
            size_t gofs = (size_t)(n0 + r) * 256 + c * 64 + c8;
            uint32_t off = r * STRB + c8 * 2;
            *(uint4*)(smem + SM_BHI + off) = *(const uint4*)(WtH + gofs);
            *(uint4*)(smem + SM_BLO + off) = *(const uint4*)(WtL + gofs);
        }
        __syncthreads();

        #pragma unroll
        for (int ks = 0; ks < 4; ks++) {
            const int k0 = ks * 16;
            uint32_t ahi[4][4], alo[4][4], bhi[2][2], blo[2][2];
            #pragma unroll
            for (int mt = 0; mt < 4; mt++) {
                uint32_t off = (a_row + mt * 16) * STRB + (k0 + a_koff) * 2;
                ldm_x4(sAhi + off, ahi[mt][0], ahi[mt][1], ahi[mt][2], ahi[mt][3]);
                ldm_x4(sAlo + off, alo[mt][0], alo[mt][1], alo[mt][2], alo[mt][3]);
            }
            #pragma unroll
            for (int nt = 0; nt < 2; nt++) {
                uint32_t off = (b_row + nt * 8) * STRB + (k0 + b_koff) * 2;
                ldm_x2(sBhi + off, bhi[nt][0], bhi[nt][1]);
                ldm_x2(sBlo + off, blo[nt][0], blo[nt][1]);
            }
            #pragma unroll
            for (int mt = 0; mt < 4; mt++)
                #pragma unroll
                for (int nt = 0; nt < 2; nt++) {
                    mma_bf16(acc[mt][nt], ahi[mt], bhi[nt]);
                    mma_bf16(acc[mt][nt], ahi[mt], blo[nt]);
                    mma_bf16(acc[mt][nt], alo[mt], bhi[nt]);
                }
        }
        __syncthreads();
    }

    // ---- epilogue ----
    float* C;
    int ldc;
    const float* bs;
    if (MODE == 0)      { C = g_value; ldc = 256; bs = bias; }
    else if (MODE == 1) { C = Cout;    ldc = 256; bs = bias; }
    else                { C = g_logit; ldc = 128; bs = g_bcat; }

    const int col_base = n0 + wid * 16;
    #pragma unroll
    for (int nt = 0; nt < 2; nt++) {
        const int col = col_base + nt * 8 + (lane & 3) * 2;
        float2 bv = *(const float2*)(bs + col);   // MODE 2: n0==0 -> direct index
        #pragma unroll
        for (int mt = 0; mt < 4; mt++) {
            int r0 = m0 + mt * 16 + (lane >> 2);
            float2 o0, o1;
            o0.x = acc[mt][nt][0] + bv.x; o0.y = acc[mt][nt][1] + bv.y;
            o1.x = acc[mt][nt][2] + bv.x; o1.y = acc[mt][nt][3] + bv.y;
            *(float2*)(C + (size_t)r0 * ldc + col)       = o0;
            *(float2*)(C + (size_t)(r0 + 8) * ldc + col) = o1;
        }
    }
}

// ----------------------------------------------------------------------------
// Sample kernel: softmax + nearest index + float4 gather -> g_mid (bf16 split).
// 32 queries / block, 256 threads.
// ----------------------------------------------------------------------------
__global__ void __launch_bounds__(256) sample_kernel(const float* __restrict__ refpts)
{
    __shared__ float logit[32][96];       // 12 KB
    __shared__ float ws16[32][8][16];     // 16 KB (per-sample weights)
    __shared__ int   vrow[32][8][16];     // 16 KB
    __shared__ float refs[32][4][2];      // 1 KB

    const int t = threadIdx.x;
    const long long gq0 = (long long)blockIdx.x * 32;

    // ---- load logits (32 rows x 96 cols), refs ----
    #pragma unroll
    for (int i = 0; i < 3; i++) {
        int idx = t + i * 256;            // 768 float4 slots
        int r = idx / 24, cq = (idx % 24) * 4;
        *(float4*)&logit[r][cq] = *(const float4*)(g_logit + (gq0 + r) * 128 + cq);
    }
    ((float*)refs)[t] = refpts[gq0 * 8 + t];
    __syncthreads();

    // ---- softmax + indices + weight expansion: one thread per (row, head) ----
    {
        const int r = t >> 3, h = t & 7;
        const long long gq = gq0 + r;
        const int b = (int)(gq / LQ);

        float l[4];
        float mx = -1e30f;
        #pragma unroll
        for (int p = 0; p < 4; p++) { l[p] = logit[r][64 + h * 4 + p]; mx = fmaxf(mx, l[p]); }
        float s = 0.f;
        #pragma unroll
        for (int p = 0; p < 4; p++) { l[p] = expf(l[p] - mx); s += l[p]; }
        float inv = 1.0f / s;

        const int DIMS[4]  = {128, 64, 32, 16};
        const int START[4] = {0, 16384, 20480, 21504};
        #pragma unroll
        for (int lvl = 0; lvl < 4; lvl++) {
            float rx = refs[r][lvl][0];
            float ry = refs[r][lvl][1];
            int Wl = DIMS[lvl];
            #pragma unroll
            for (int p = 0; p < 4; p++) {
                float ox = logit[r][h * 8 + p * 2 + 0];
                float oy = logit[r][h * 8 + p * 2 + 1];
                float sx = fminf(fmaxf(rx + ox, 0.f), 1.f);
                float sy = fminf(fmaxf(ry + oy, 0.f), 1.f);
                int x0 = (int)floorf(sx * (float)(Wl - 1));
                int y0 = (int)floorf(sy * (float)(Wl - 1));
                vrow[r][h][p * 4 + lvl] = b * LQ + START[lvl] + y0 * Wl + x0;
                ws16[r][h][p * 4 + lvl] = l[p] * inv;
            }
        }
    }
    __syncthreads();

    // ---- gather: warp w -> rows 4w..4w+3; lane covers (head, 4-channel quad) ----
    {
        const int w = t >> 5, lane = t & 31;
        const int hh = lane >> 3;            // head within group of 4
        const int c4 = (lane & 7) * 4;       // channel quad within head
        #pragma unroll
        for (int rw = 0; rw < 4; rw++) {
            const int r = w * 4 + rw;
            #pragma unroll
            for (int hg = 0; hg < 2; hg++) {
                const int h = hg * 4 + hh;
                const int coff = h * 32 + c4;
                const int* vr = vrow[r][h];
                const float* wsv = ws16[r][h];
                float4 acc = make_float4(0.f, 0.f, 0.f, 0.f);
                #pragma unroll
                for (int s = 0; s < 16; s++) {
                    float4 vv = *(const float4*)(g_value + (size_t)vr[s] * 256 + coff);
                    float wgt = wsv[s];
                    acc.x += wgt * vv.x; acc.y += wgt * vv.y;
                    acc.z += wgt * vv.z; acc.w += wgt * vv.w;
                }
                // Dekker split -> packed bf16 stores (4 ch = 8B per array)
                uint32_t h01 = bf2(acc.x, acc.y);
                uint32_t h23 = bf2(acc.z, acc.w);
                float hx = __uint_as_float(h01 << 16);
                float hy = __uint_as_float(h01 & 0xffff0000u);
                float hz = __uint_as_float(h23 << 16);
                float hw = __uint_as_float(h23 & 0xffff0000u);
                uint32_t l01 = bf2(acc.x - hx, acc.y - hy);
                uint32_t l23 = bf2(acc.z - hz, acc.w - hw);
                size_t o = (size_t)(gq0 + r) * 256 + coff;
                *(uint2*)(g_mid_hi + o) = make_uint2(h01, h23);
                *(uint2*)(g_mid_lo + o) = make_uint2(l01, l23);
            }
        }
    }
}

// ----------------------------------------------------------------------------
extern "C" void kernel_launch(void* const* d_in, const int* in_sizes, int n_in,
                              void* d_out, int out_size)
{
    (void)in_sizes; (void)n_in; (void)out_size;
    const float* query  = (const float*)d_in[0];
    const float* refpts = (const float*)d_in[1];
    const float* f0     = (const float*)d_in[2];
    const float* f1     = (const float*)d_in[3];
    const float* f2     = (const float*)d_in[4];
    const float* f3     = (const float*)d_in[5];
    const float* W_off  = (const float*)d_in[6];
    const float* b_off  = (const float*)d_in[7];
    const float* W_attn = (const float*)d_in[8];
    const float* b_attn = (const float*)d_in[9];
    const float* W_val  = (const float*)d_in[10];
    const float* b_val  = (const float*)d_in[11];
    const float* W_out  = (const float*)d_in[12];
    const float* b_out  = (const float*)d_in[13];
    float* out = (float*)d_out;

    cudaFuncSetAttribute(gemm_mma<0>, cudaFuncAttributeMaxDynamicSharedMemorySize, SMEM_TOTAL);
    cudaFuncSetAttribute(gemm_mma<1>, cudaFuncAttributeMaxDynamicSharedMemorySize, SMEM_TOTAL);
    cudaFuncSetAttribute(gemm_mma<2>, cudaFuncAttributeMaxDynamicSharedMemorySize, SMEM_TOTAL);

    prep_kernel<<<256, 256>>>(W_val, W_out, W_off, W_attn, b_off, b_attn);

    dim3 g2(M_TOTAL / 64, 2);
    dim3 g1(M_TOTAL / 64, 1);
    // logits GEMM (query @ [W_off|W_attn|0]) -> g_logit
    gemm_mma<2><<<g1, 256, SMEM_TOTAL>>>(query, nullptr, nullptr, nullptr, nullptr, nullptr);
    // value projection -> g_value
    gemm_mma<0><<<g2, 256, SMEM_TOTAL>>>(f0, f1, f2, f3, b_val, nullptr);
    // softmax + gather -> g_mid (bf16 split)
    sample_kernel<<<M_TOTAL / 32, 256>>>(refpts);
    // output projection -> out
    gemm_mma<1><<<g2, 256, SMEM_TOTAL>>>(nullptr, nullptr, nullptr, nullptr, b_out, out);
}

// round 8
// speedup vs baseline: 2.3059x; 1.0869x over previous
#include <cuda_runtime.h>
#include <cuda_bf16.h>
#include <cuda_fp16.h>
#include <cstdint>
#include <cstddef>

// ============================================================================
// DeformableAttention: B=4, Lq=21760, DIM=256, NH=8, NP=4, HD=32
// Levels: (128,128),(64,64),(32,32),(16,16) -> Lv = 21760, starts 0/16384/20480/21504
// M = B*Lq = B*Lv = 87040
// value/logit GEMMs: bf16 3-term split.  out GEMM: fp16 2-term (W split).
// g_value, g_mid held in fp16 to halve gather/L2 traffic.
// ============================================================================

#define M_TOTAL 87040
#define LQ 21760

__device__ __half         g_val16[(size_t)M_TOTAL * 256];
__device__ __half         g_mid16[(size_t)M_TOTAL * 256];
__device__ float          g_logit[(size_t)M_TOTAL * 96];    // 0-63 off, 64-95 attn
// bf16 transposed hi/lo weights [slot][n*256+k]: 0=W_val, 1=cat(W_off|W_attn|0)
__device__ __nv_bfloat16  g_Wt_hi[2][256 * 256];
__device__ __nv_bfloat16  g_Wt_lo[2][256 * 256];
// fp16 transposed hi/lo W_out
__device__ __half         g_W16_hi[256 * 256];
__device__ __half         g_W16_lo[256 * 256];
__device__ float          g_bcat[128];

// ---------------------------------------------------------------------------
__device__ __forceinline__ uint32_t smem_to_u32(const void* p) {
    uint32_t a;
    asm("{ .reg .u64 t; cvta.to.shared.u64 t, %1; cvt.u32.u64 %0, t; }" : "=r"(a) : "l"(p));
    return a;
}
__device__ __forceinline__ uint32_t bf2(float x, float y) {   // lo=x, hi=y
    uint32_t r;
    asm("cvt.rn.bf16x2.f32 %0, %1, %2;" : "=r"(r) : "f"(y), "f"(x));
    return r;
}
__device__ __forceinline__ void ldm_x4(uint32_t addr, uint32_t& r0, uint32_t& r1,
                                       uint32_t& r2, uint32_t& r3) {
    asm volatile("ldmatrix.sync.aligned.m8n8.x4.shared.b16 {%0,%1,%2,%3}, [%4];"
                 : "=r"(r0), "=r"(r1), "=r"(r2), "=r"(r3) : "r"(addr));
}
__device__ __forceinline__ void ldm_x2(uint32_t addr, uint32_t& r0, uint32_t& r1) {
    asm volatile("ldmatrix.sync.aligned.m8n8.x2.shared.b16 {%0,%1}, [%2];"
                 : "=r"(r0), "=r"(r1) : "r"(addr));
}
__device__ __forceinline__ void mma_bf16(float* d, const uint32_t* a, const uint32_t* b) {
    asm volatile("mma.sync.aligned.m16n8k16.row.col.f32.bf16.bf16.f32 "
                 "{%0,%1,%2,%3}, {%4,%5,%6,%7}, {%8,%9}, {%0,%1,%2,%3};"
                 : "+f"(d[0]), "+f"(d[1]), "+f"(d[2]), "+f"(d[3])
                 : "r"(a[0]), "r"(a[1]), "r"(a[2]), "r"(a[3]), "r"(b[0]), "r"(b[1]));
}
__device__ __forceinline__ void mma_f16(float* d, const uint32_t* a, const uint32_t* b) {
    asm volatile("mma.sync.aligned.m16n8k16.row.col.f32.f16.f16.f32 "
                 "{%0,%1,%2,%3}, {%4,%5,%6,%7}, {%8,%9}, {%0,%1,%2,%3};"
                 : "+f"(d[0]), "+f"(d[1]), "+f"(d[2]), "+f"(d[3])
                 : "r"(a[0]), "r"(a[1]), "r"(a[2]), "r"(a[3]), "r"(b[0]), "r"(b[1]));
}

// ---------------------------------------------------------------------------
// prep: transpose + split all weights; concatenated logit bias
// ---------------------------------------------------------------------------
__global__ void __launch_bounds__(256) prep_kernel(
    const float* __restrict__ Wv, const float* __restrict__ Wo,
    const float* __restrict__ Woff, const float* __restrict__ Wattn,
    const float* __restrict__ boff, const float* __restrict__ battn)
{
    int k = blockIdx.x;       // 0..255
    int n = threadIdx.x;      // 0..255
    {
        float v = Wv[k * 256 + n];
        __nv_bfloat16 h = __float2bfloat16_rn(v);
        g_Wt_hi[0][n * 256 + k] = h;
        g_Wt_lo[0][n * 256 + k] = __float2bfloat16_rn(v - __bfloat162float(h));
    }
    {
        float v = Wo[k * 256 + n];
        __half h = __float2half_rn(v);
        g_W16_hi[n * 256 + k] = h;
        g_W16_lo[n * 256 + k] = __float2half_rn(v - __half2float(h));
    }
    if (n < 128) {
        float v = 0.f;
        if (n < 64)      v = Woff[k * 64 + n];
        else if (n < 96) v = Wattn[k * 32 + (n - 64)];
        __nv_bfloat16 h = __float2bfloat16_rn(v);
        g_Wt_hi[1][n * 256 + k] = h;
        g_Wt_lo[1][n * 256 + k] = __float2bfloat16_rn(v - __bfloat162float(h));
        if (k == 0) {
            float bb = 0.f;
            if (n < 64)      bb = boff[n];
            else if (n < 96) bb = battn[n - 64];
            g_bcat[n] = bb;
        }
    }
}

// ---------------------------------------------------------------------------
// Unified mma.sync GEMM. CTA tile M=64, N=128. K chunks of 64.
// 256 threads = 8 warps, warp tile 64x16.
// MODE 0: A = feats (fp32->bf16 split, 3-term) -> g_val16 (fp16) [grid.y=2]
// MODE 1: A = g_mid16 (fp16, 2-term W split)   -> Cout fp32      [grid.y=2]
// MODE 2: A = query (fp32->bf16 split, 3-term) -> g_logit (ldc=96)
// ---------------------------------------------------------------------------
#define STRB 144
#define SM_ROWPTR 0
#define SM_AHI 512
#define SM_ALO (SM_AHI + 64 * STRB)
#define SM_BHI (SM_ALO + 64 * STRB)
#define SM_BLO (SM_BHI + 128 * STRB)
#define SMEM_TOTAL (SM_BLO + 128 * STRB)   // 55808 B

template<int MODE>
__global__ void __launch_bounds__(256, 2) gemm_mma(
    const float* __restrict__ f0, const float* __restrict__ f1,
    const float* __restrict__ f2, const float* __restrict__ f3,
    const float* __restrict__ bias, float* __restrict__ Cout)
{
    extern __shared__ char smem[];
    const int t = threadIdx.x;
    const int wid = t >> 5, lane = t & 31;
    const int m0 = blockIdx.x * 64;
    const int n0 = blockIdx.y * 128;

    const float** rowptr = (const float**)(smem + SM_ROWPTR);
    if (MODE != 1 && t < 64) {
        int r = m0 + t;
        const float* p;
        if (MODE == 0) {
            int b = r / LQ;
            int l = r - b * LQ;
            if (l < 16384)      p = f0 + ((size_t)b * 16384 + l) * 256;
            else if (l < 20480) p = f1 + ((size_t)b * 4096 + (l - 16384)) * 256;
            else if (l < 21504) p = f2 + ((size_t)b * 1024 + (l - 20480)) * 256;
            else                p = f3 + ((size_t)b * 256  + (l - 21504)) * 256;
        } else {
            p = f0 + (size_t)r * 256;   // query
        }
        rowptr[t] = p;
    }
    if (MODE != 1) __syncthreads();

    const __nv_bfloat16* WtH = (MODE == 0) ? g_Wt_hi[0] : g_Wt_hi[1];
    const __nv_bfloat16* WtL = (MODE == 0) ? g_Wt_lo[0] : g_Wt_lo[1];

    uint32_t sb = smem_to_u32(smem);
    const uint32_t sAhi = sb + SM_AHI, sAlo = sb + SM_ALO;
    const uint32_t sBhi = sb + SM_BHI, sBlo = sb + SM_BLO;

    const uint32_t a_row = lane & 15;
    const uint32_t a_koff = (lane >> 4) * 8;
    const uint32_t b_row = wid * 16 + (lane & 7);
    const uint32_t b_koff = ((lane >> 3) & 1) * 8;

    float acc[4][2][4];
    #pragma unroll
    for (int i = 0; i < 4; i++)
        #pragma unroll
        for (int j = 0; j < 2; j++)
            #pragma unroll
            for (int e = 0; e < 4; e++) acc[i][j][e] = 0.f;

    for (int c = 0; c < 4; c++) {
        // ---- A chunk: 64 rows x 64 k ----
        if (MODE == 1) {
            #pragma unroll
            for (int i = 0; i < 2; i++) {
                int idx = t + i * 256;                // 512 uint4 slots (8 halves)
                int r = idx >> 3, c8 = (idx & 7) * 8;
                *(uint4*)(smem + SM_AHI + r * STRB + c8 * 2) =
                    *(const uint4*)(g_mid16 + (size_t)(m0 + r) * 256 + c * 64 + c8);
            }
        } else {
            #pragma unroll
            for (int i = 0; i < 4; i++) {
                int idx = t + i * 256;                // 1024 float4 slots
                int r = idx >> 4, c4 = (idx & 15) * 4;
                float4 v = *(const float4*)(rowptr[r] + c * 64 + c4);
                uint32_t h01 = bf2(v.x, v.y);
                uint32_t h23 = bf2(v.z, v.w);
                float hx = __uint_as_float(h01 << 16);
                float hy = __uint_as_float(h01 & 0xffff0000u);
                float hz = __uint_as_float(h23 << 16);
                float hw = __uint_as_float(h23 & 0xffff0000u);
                uint32_t l01 = bf2(v.x - hx, v.y - hy);
                uint32_t l23 = bf2(v.z - hz, v.w - hw);
                uint32_t off = r * STRB + c4 * 2;
                *(uint2*)(smem + SM_AHI + off) = make_uint2(h01, h23);
                *(uint2*)(smem + SM_ALO + off) = make_uint2(l01, l23);
            }
        }
        // ---- B chunk: 128 n-rows x 64 k ----
        #pragma unroll
        for (int i = 0; i < 4; i++) {
            int idx = t + i * 256;                    // 1024 uint4 slots
            int r = idx >> 3, c8 = (idx & 7) * 8;
            size_t gofs = (size_t)(n0 + r) * 256 + c * 64 + c8;
            uint32_t off = r * STRB + c8 * 2;
            if (MODE == 1) {
                *(uint4*)(smem + SM_BHI + off) = *(const uint4*)(g_W16_hi + gofs);
                *(uint4*)(smem + SM_BLO + off) = *(const uint4*)(g_W16_lo + gofs);
            } else {
                *(uint4*)(smem + SM_BHI + off) = *(const uint4*)(WtH + gofs);
                *(uint4*)(smem + SM_BLO + off) = *(const uint4*)(WtL + gofs);
            }
        }
        __syncthreads();

        #pragma unroll
        for (int ks = 0; ks < 4; ks++) {
            const int k0 = ks * 16;
            uint32_t ahi[4][4], alo[4][4], bhi[2][2], blo[2][2];
            #pragma unroll
            for (int mt = 0; mt < 4; mt++) {
                uint32_t off = (a_row + mt * 16) * STRB + (k0 + a_koff) * 2;
                ldm_x4(sAhi + off, ahi[mt][0], ahi[mt][1], ahi[mt][2], ahi[mt][3]);
                if (MODE != 1)
                    ldm_x4(sAlo + off, alo[mt][0], alo[mt][1], alo[mt][2], alo[mt][3]);
            }
            #pragma unroll
            for (int nt = 0; nt < 2; nt++) {
                uint32_t off = (b_row + nt * 8) * STRB + (k0 + b_koff) * 2;
                ldm_x2(sBhi + off, bhi[nt][0], bhi[nt][1]);
                ldm_x2(sBlo + off, blo[nt][0], blo[nt][1]);
            }
            #pragma unroll
            for (int mt = 0; mt < 4; mt++)
                #pragma unroll
                for (int nt = 0; nt < 2; nt++) {
                    if (MODE == 1) {
                        mma_f16(acc[mt][nt], ahi[mt], bhi[nt]);
                        mma_f16(acc[mt][nt], ahi[mt], blo[nt]);
                    } else {
                        mma_bf16(acc[mt][nt], ahi[mt], bhi[nt]);
                        mma_bf16(acc[mt][nt], ahi[mt], blo[nt]);
                        mma_bf16(acc[mt][nt], alo[mt], bhi[nt]);
                    }
                }
        }
        __syncthreads();
    }

    // ---- epilogue ----
    const int col_base = n0 + wid * 16;
    #pragma unroll
    for (int nt = 0; nt < 2; nt++) {
        const int col = col_base + nt * 8 + (lane & 3) * 2;
        if (MODE == 2 && col >= 96) continue;
        float2 bv = make_float2(0.f, 0.f);
        if (MODE == 1) bv = *(const float2*)(bias + col);
        if (MODE == 2) bv = *(const float2*)(g_bcat + col);
        #pragma unroll
        for (int mt = 0; mt < 4; mt++) {
            int r0 = m0 + mt * 16 + (lane >> 2);
            float2 o0, o1;
            o0.x = acc[mt][nt][0] + bv.x; o0.y = acc[mt][nt][1] + bv.y;
            o1.x = acc[mt][nt][2] + bv.x; o1.y = acc[mt][nt][3] + bv.y;
            if (MODE == 0) {
                // + bias (b_val) then fp16
                float2 b2 = *(const float2*)(bias + col);
                *(__half2*)(g_val16 + (size_t)r0 * 256 + col) =
                    __floats2half2_rn(o0.x + b2.x, o0.y + b2.y);
                *(__half2*)(g_val16 + (size_t)(r0 + 8) * 256 + col) =
                    __floats2half2_rn(o1.x + b2.x, o1.y + b2.y);
            } else if (MODE == 1) {
                *(float2*)(Cout + (size_t)r0 * 256 + col)       = o0;
                *(float2*)(Cout + (size_t)(r0 + 8) * 256 + col) = o1;
            } else {
                *(float2*)(g_logit + (size_t)r0 * 96 + col)       = o0;
                *(float2*)(g_logit + (size_t)(r0 + 8) * 96 + col) = o1;
            }
        }
    }
}

// ----------------------------------------------------------------------------
// Sample kernel: softmax + nearest index + fp16 gather -> g_mid16.
// 32 queries / block, 256 threads. Lane = (head, 8-channel group).
// ----------------------------------------------------------------------------
__global__ void __launch_bounds__(256) sample_kernel(const float* __restrict__ refpts)
{
    __shared__ float logit[32][96];       // 12 KB
    __shared__ float ws16[32][8][16];     // 16 KB
    __shared__ int   vrow[32][8][16];     // 16 KB
    __shared__ float refs[32][4][2];      // 1 KB

    const int t = threadIdx.x;
    const long long gq0 = (long long)blockIdx.x * 32;

    // ---- load logits (32 rows x 96 cols), refs ----
    #pragma unroll
    for (int i = 0; i < 3; i++) {
        int idx = t + i * 256;            // 768 float4 slots
        int r = idx / 24, cq = (idx % 24) * 4;
        *(float4*)&logit[r][cq] = *(const float4*)(g_logit + (gq0 + r) * 96 + cq);
    }
    ((float*)refs)[t] = refpts[gq0 * 8 + t];
    __syncthreads();

    // ---- softmax + indices + weight expansion: one thread per (row, head) ----
    {
        const int r = t >> 3, h = t & 7;
        const long long gq = gq0 + r;
        const int b = (int)(gq / LQ);

        float l[4];
        float mx = -1e30f;
        #pragma unroll
        for (int p = 0; p < 4; p++) { l[p] = logit[r][64 + h * 4 + p]; mx = fmaxf(mx, l[p]); }
        float s = 0.f;
        #pragma unroll
        for (int p = 0; p < 4; p++) { l[p] = expf(l[p] - mx); s += l[p]; }
        float inv = 1.0f / s;

        const int DIMS[4]  = {128, 64, 32, 16};
        const int START[4] = {0, 16384, 20480, 21504};
        #pragma unroll
        for (int lvl = 0; lvl < 4; lvl++) {
            float rx = refs[r][lvl][0];
            float ry = refs[r][lvl][1];
            int Wl = DIMS[lvl];
            #pragma unroll
            for (int p = 0; p < 4; p++) {
                float ox = logit[r][h * 8 + p * 2 + 0];
                float oy = logit[r][h * 8 + p * 2 + 1];
                float sx = fminf(fmaxf(rx + ox, 0.f), 1.f);
                float sy = fminf(fmaxf(ry + oy, 0.f), 1.f);
                int x0 = (int)floorf(sx * (float)(Wl - 1));
                int y0 = (int)floorf(sy * (float)(Wl - 1));
                vrow[r][h][p * 4 + lvl] = b * LQ + START[lvl] + y0 * Wl + x0;
                ws16[r][h][p * 4 + lvl] = l[p] * inv;
            }
        }
    }
    __syncthreads();

    // ---- gather: warp w -> rows 4w..4w+3; lane = head (lane>>2) x 8-ch group ----
    {
        const int w = t >> 5, lane = t & 31;
        const int h = lane >> 2;             // 0..7
        const int c8 = (lane & 3) * 8;       // channel group within head
        const int coff = h * 32 + c8;
        #pragma unroll
        for (int rw = 0; rw < 4; rw++) {
            const int r = w * 4 + rw;
            const int* vr = vrow[r][h];
            const float* wsv = ws16[r][h];
            float acc[8] = {0.f, 0.f, 0.f, 0.f, 0.f, 0.f, 0.f, 0.f};
            #pragma unroll
            for (int s = 0; s < 16; s++) {
                uint4 u = *(const uint4*)(g_val16 + (size_t)vr[s] * 256 + coff);
                float wgt = wsv[s];
                const __half2* hp = (const __half2*)&u;
                #pragma unroll
                for (int e = 0; e < 4; e++) {
                    float2 f = __half22float2(hp[e]);
                    acc[2 * e]     += wgt * f.x;
                    acc[2 * e + 1] += wgt * f.y;
                }
            }
            __half2 o[4];
            #pragma unroll
            for (int e = 0; e < 4; e++)
                o[e] = __floats2half2_rn(acc[2 * e], acc[2 * e + 1]);
            *(uint4*)(g_mid16 + (size_t)(gq0 + r) * 256 + coff) = *(uint4*)o;
        }
    }
}

// ----------------------------------------------------------------------------
extern "C" void kernel_launch(void* const* d_in, const int* in_sizes, int n_in,
                              void* d_out, int out_size)
{
    (void)in_sizes; (void)n_in; (void)out_size;
    const float* query  = (const float*)d_in[0];
    const float* refpts = (const float*)d_in[1];
    const float* f0     = (const float*)d_in[2];
    const float* f1     = (const float*)d_in[3];
    const float* f2     = (const float*)d_in[4];
    const float* f3     = (const float*)d_in[5];
    const float* W_off  = (const float*)d_in[6];
    const float* b_off  = (const float*)d_in[7];
    const float* W_attn = (const float*)d_in[8];
    const float* b_attn = (const float*)d_in[9];
    const float* W_val  = (const float*)d_in[10];
    const float* b_val  = (const float*)d_in[11];
    const float* W_out  = (const float*)d_in[12];
    const float* b_out  = (const float*)d_in[13];
    float* out = (float*)d_out;

    cudaFuncSetAttribute(gemm_mma<0>, cudaFuncAttributeMaxDynamicSharedMemorySize, SMEM_TOTAL);
    cudaFuncSetAttribute(gemm_mma<1>, cudaFuncAttributeMaxDynamicSharedMemorySize, SMEM_TOTAL);
    cudaFuncSetAttribute(gemm_mma<2>, cudaFuncAttributeMaxDynamicSharedMemorySize, SMEM_TOTAL);

    prep_kernel<<<256, 256>>>(W_val, W_out, W_off, W_attn, b_off, b_attn);

    dim3 g2(M_TOTAL / 64, 2);
    dim3 g1(M_TOTAL / 64, 1);
    // logits GEMM (query @ [W_off|W_attn|0]) -> g_logit
    gemm_mma<2><<<g1, 256, SMEM_TOTAL>>>(query, nullptr, nullptr, nullptr, nullptr, nullptr);
    // value projection -> g_val16
    gemm_mma<0><<<g2, 256, SMEM_TOTAL>>>(f0, f1, f2, f3, b_val, nullptr);
    // softmax + gather -> g_mid16
    sample_kernel<<<M_TOTAL / 32, 256>>>(refpts);
    // output projection -> out
    gemm_mma<1><<<g2, 256, SMEM_TOTAL>>>(nullptr, nullptr, nullptr, nullptr, b_out, out);
}

// round 9
// speedup vs baseline: 2.8011x; 1.2148x over previous
#include <cuda_runtime.h>
#include <cuda_bf16.h>
#include <cuda_fp16.h>
#include <cstdint>
#include <cstddef>

// ============================================================================
// DeformableAttention: B=4, Lq=21760, DIM=256, NH=8, NP=4, HD=32
// Levels: (128,128),(64,64),(32,32),(16,16) -> Lv = 21760, starts 0/16384/20480/21504
// M = B*Lq = B*Lv = 87040
// All GEMMs: A in fp16, W as fp16 Dekker hi/lo, 2-term f16 MMA, fp32 accum.
// g_value, g_mid in fp16 (halves gather/L2 traffic).
// ============================================================================

#define M_TOTAL 87040
#define LQ 21760

__device__ __half  g_val16[(size_t)M_TOTAL * 256];
__device__ __half  g_mid16[(size_t)M_TOTAL * 256];
__device__ float   g_logit[(size_t)M_TOTAL * 96];    // 0-63 off, 64-95 attn
// fp16 transposed hi/lo weights [slot][n*256+k]: 0=W_val, 1=W_out, 2=cat(W_off|W_attn|0)
__device__ __half  g_W16_hi[3][256 * 256];
__device__ __half  g_W16_lo[3][256 * 256];
__device__ float   g_bcat[128];

// ---------------------------------------------------------------------------
__device__ __forceinline__ uint32_t smem_to_u32(const void* p) {
    uint32_t a;
    asm("{ .reg .u64 t; cvta.to.shared.u64 t, %1; cvt.u32.u64 %0, t; }" : "=r"(a) : "l"(p));
    return a;
}
__device__ __forceinline__ uint32_t h2u(__half2 h) {
    return *reinterpret_cast<uint32_t*>(&h);
}
__device__ __forceinline__ void ldm_x4(uint32_t addr, uint32_t& r0, uint32_t& r1,
                                       uint32_t& r2, uint32_t& r3) {
    asm volatile("ldmatrix.sync.aligned.m8n8.x4.shared.b16 {%0,%1,%2,%3}, [%4];"
                 : "=r"(r0), "=r"(r1), "=r"(r2), "=r"(r3) : "r"(addr));
}
__device__ __forceinline__ void ldm_x2(uint32_t addr, uint32_t& r0, uint32_t& r1) {
    asm volatile("ldmatrix.sync.aligned.m8n8.x2.shared.b16 {%0,%1}, [%2];"
                 : "=r"(r0), "=r"(r1) : "r"(addr));
}
__device__ __forceinline__ void mma_f16(float* d, const uint32_t* a, const uint32_t* b) {
    asm volatile("mma.sync.aligned.m16n8k16.row.col.f32.f16.f16.f32 "
                 "{%0,%1,%2,%3}, {%4,%5,%6,%7}, {%8,%9}, {%0,%1,%2,%3};"
                 : "+f"(d[0]), "+f"(d[1]), "+f"(d[2]), "+f"(d[3])
                 : "r"(a[0]), "r"(a[1]), "r"(a[2]), "r"(a[3]), "r"(b[0]), "r"(b[1]));
}

// ---------------------------------------------------------------------------
// prep: transpose + fp16 Dekker split all weights; concatenated logit bias
// ---------------------------------------------------------------------------
__global__ void __launch_bounds__(256) prep_kernel(
    const float* __restrict__ Wv, const float* __restrict__ Wo,
    const float* __restrict__ Woff, const float* __restrict__ Wattn,
    const float* __restrict__ boff, const float* __restrict__ battn)
{
    int k = blockIdx.x;       // 0..255
    int n = threadIdx.x;      // 0..255
    {
        float v = Wv[k * 256 + n];
        __half h = __float2half_rn(v);
        g_W16_hi[0][n * 256 + k] = h;
        g_W16_lo[0][n * 256 + k] = __float2half_rn(v - __half2float(h));
    }
    {
        float v = Wo[k * 256 + n];
        __half h = __float2half_rn(v);
        g_W16_hi[1][n * 256 + k] = h;
        g_W16_lo[1][n * 256 + k] = __float2half_rn(v - __half2float(h));
    }
    if (n < 128) {
        float v = 0.f;
        if (n < 64)      v = Woff[k * 64 + n];
        else if (n < 96) v = Wattn[k * 32 + (n - 64)];
        __half h = __float2half_rn(v);
        g_W16_hi[2][n * 256 + k] = h;
        g_W16_lo[2][n * 256 + k] = __float2half_rn(v - __half2float(h));
        if (k == 0) {
            float bb = 0.f;
            if (n < 64)      bb = boff[n];
            else if (n < 96) bb = battn[n - 64];
            g_bcat[n] = bb;
        }
    }
}

// ---------------------------------------------------------------------------
// Unified mma.sync GEMM. CTA tile M=64, N=128. K chunks of 64.
// 256 threads = 8 warps, warp tile 64x16. 2-term f16 MMA (W hi/lo).
// MODE 0: A = feats (fp32->f16)  -> g_val16 (fp16, +b_val) [grid.y=2]
// MODE 1: A = g_mid16 (copy)     -> Cout fp32 (+b_out)     [grid.y=2]
// MODE 2: A = query (fp32->f16)  -> g_logit (ldc=96, +bcat)
// ---------------------------------------------------------------------------
#define STRB 144
#define SM_ROWPTR 0
#define SM_AHI 512
#define SM_BHI (SM_AHI + 64 * STRB)
#define SM_BLO (SM_BHI + 128 * STRB)
#define SMEM_TOTAL (SM_BLO + 128 * STRB)   // 46.6 KB

template<int MODE>
__global__ void __launch_bounds__(256, 3) gemm_mma(
    const float* __restrict__ f0, const float* __restrict__ f1,
    const float* __restrict__ f2, const float* __restrict__ f3,
    const float* __restrict__ bias, float* __restrict__ Cout)
{
    extern __shared__ char smem[];
    const int t = threadIdx.x;
    const int wid = t >> 5, lane = t & 31;
    const int m0 = blockIdx.x * 64;
    const int n0 = blockIdx.y * 128;

    const float** rowptr = (const float**)(smem + SM_ROWPTR);
    if (MODE != 1 && t < 64) {
        int r = m0 + t;
        const float* p;
        if (MODE == 0) {
            int b = r / LQ;
            int l = r - b * LQ;
            if (l < 16384)      p = f0 + ((size_t)b * 16384 + l) * 256;
            else if (l < 20480) p = f1 + ((size_t)b * 4096 + (l - 16384)) * 256;
            else if (l < 21504) p = f2 + ((size_t)b * 1024 + (l - 20480)) * 256;
            else                p = f3 + ((size_t)b * 256  + (l - 21504)) * 256;
        } else {
            p = f0 + (size_t)r * 256;   // query
        }
        rowptr[t] = p;
    }
    if (MODE != 1) __syncthreads();

    const int slot = (MODE == 0) ? 0 : (MODE == 1) ? 1 : 2;
    const __half* WtH = g_W16_hi[slot];
    const __half* WtL = g_W16_lo[slot];

    uint32_t sb = smem_to_u32(smem);
    const uint32_t sAhi = sb + SM_AHI;
    const uint32_t sBhi = sb + SM_BHI, sBlo = sb + SM_BLO;

    const uint32_t a_row = lane & 15;
    const uint32_t a_koff = (lane >> 4) * 8;
    const uint32_t b_row = wid * 16 + (lane & 7);
    const uint32_t b_koff = ((lane >> 3) & 1) * 8;

    float acc[4][2][4];
    #pragma unroll
    for (int i = 0; i < 4; i++)
        #pragma unroll
        for (int j = 0; j < 2; j++)
            #pragma unroll
            for (int e = 0; e < 4; e++) acc[i][j][e] = 0.f;

    for (int c = 0; c < 4; c++) {
        // ---- A chunk: 64 rows x 64 k (fp16) ----
        if (MODE == 1) {
            #pragma unroll
            for (int i = 0; i < 2; i++) {
                int idx = t + i * 256;                // 512 uint4 slots (8 halves)
                int r = idx >> 3, c8 = (idx & 7) * 8;
                *(uint4*)(smem + SM_AHI + r * STRB + c8 * 2) =
                    *(const uint4*)(g_mid16 + (size_t)(m0 + r) * 256 + c * 64 + c8);
            }
        } else {
            #pragma unroll
            for (int i = 0; i < 4; i++) {
                int idx = t + i * 256;                // 1024 float4 slots
                int r = idx >> 4, c4 = (idx & 15) * 4;
                float4 v = *(const float4*)(rowptr[r] + c * 64 + c4);
                uint32_t h01 = h2u(__floats2half2_rn(v.x, v.y));
                uint32_t h23 = h2u(__floats2half2_rn(v.z, v.w));
                *(uint2*)(smem + SM_AHI + r * STRB + c4 * 2) = make_uint2(h01, h23);
            }
        }
        // ---- B chunk: 128 n-rows x 64 k (hi + lo) ----
        #pragma unroll
        for (int i = 0; i < 4; i++) {
            int idx = t + i * 256;                    // 1024 uint4 slots
            int r = idx >> 3, c8 = (idx & 7) * 8;
            size_t gofs = (size_t)(n0 + r) * 256 + c * 64 + c8;
            uint32_t off = r * STRB + c8 * 2;
            *(uint4*)(smem + SM_BHI + off) = *(const uint4*)(WtH + gofs);
            *(uint4*)(smem + SM_BLO + off) = *(const uint4*)(WtL + gofs);
        }
        __syncthreads();

        #pragma unroll
        for (int ks = 0; ks < 4; ks++) {
            const int k0 = ks * 16;
            uint32_t a[4][4], bhi[2][2], blo[2][2];
            #pragma unroll
            for (int mt = 0; mt < 4; mt++) {
                uint32_t off = (a_row + mt * 16) * STRB + (k0 + a_koff) * 2;
                ldm_x4(sAhi + off, a[mt][0], a[mt][1], a[mt][2], a[mt][3]);
            }
            #pragma unroll
            for (int nt = 0; nt < 2; nt++) {
                uint32_t off = (b_row + nt * 8) * STRB + (k0 + b_koff) * 2;
                ldm_x2(sBhi + off, bhi[nt][0], bhi[nt][1]);
                ldm_x2(sBlo + off, blo[nt][0], blo[nt][1]);
            }
            #pragma unroll
            for (int mt = 0; mt < 4; mt++)
                #pragma unroll
                for (int nt = 0; nt < 2; nt++) {
                    mma_f16(acc[mt][nt], a[mt], bhi[nt]);
                    mma_f16(acc[mt][nt], a[mt], blo[nt]);
                }
        }
        __syncthreads();
    }

    // ---- epilogue ----
    const int col_base = n0 + wid * 16;
    #pragma unroll
    for (int nt = 0; nt < 2; nt++) {
        const int col = col_base + nt * 8 + (lane & 3) * 2;
        if (MODE == 2 && col >= 96) continue;
        float2 bv;
        if (MODE == 2) bv = *(const float2*)(g_bcat + col);
        else           bv = *(const float2*)(bias + col);
        #pragma unroll
        for (int mt = 0; mt < 4; mt++) {
            int r0 = m0 + mt * 16 + (lane >> 2);
            float2 o0, o1;
            o0.x = acc[mt][nt][0] + bv.x; o0.y = acc[mt][nt][1] + bv.y;
            o1.x = acc[mt][nt][2] + bv.x; o1.y = acc[mt][nt][3] + bv.y;
            if (MODE == 0) {
                *(__half2*)(g_val16 + (size_t)r0 * 256 + col)       = __floats2half2_rn(o0.x, o0.y);
                *(__half2*)(g_val16 + (size_t)(r0 + 8) * 256 + col) = __floats2half2_rn(o1.x, o1.y);
            } else if (MODE == 1) {
                *(float2*)(Cout + (size_t)r0 * 256 + col)       = o0;
                *(float2*)(Cout + (size_t)(r0 + 8) * 256 + col) = o1;
            } else {
                *(float2*)(g_logit + (size_t)r0 * 96 + col)       = o0;
                *(float2*)(g_logit + (size_t)(r0 + 8) * 96 + col) = o1;
            }
        }
    }
}

// ----------------------------------------------------------------------------
// Sample kernel: softmax + nearest index + fp16 gather -> g_mid16.
// 32 queries / block, 256 threads. Lane = (head, 8-channel group).
// ----------------------------------------------------------------------------
__global__ void __launch_bounds__(256) sample_kernel(const float* __restrict__ refpts)
{
    __shared__ float logit[32][96];       // 12 KB
    __shared__ float ws16[32][8][16];     // 16 KB
    __shared__ int   vrow[32][8][16];     // 16 KB
    __shared__ float refs[32][4][2];      // 1 KB

    const int t = threadIdx.x;
    const long long gq0 = (long long)blockIdx.x * 32;

    // ---- load logits (32 rows x 96 cols), refs ----
    #pragma unroll
    for (int i = 0; i < 3; i++) {
        int idx = t + i * 256;            // 768 float4 slots
        int r = idx / 24, cq = (idx % 24) * 4;
        *(float4*)&logit[r][cq] = *(const float4*)(g_logit + (gq0 + r) * 96 + cq);
    }
    ((float*)refs)[t] = refpts[gq0 * 8 + t];
    __syncthreads();

    // ---- softmax + indices + weight expansion: one thread per (row, head) ----
    {
        const int r = t >> 3, h = t & 7;
        const long long gq = gq0 + r;
        const int b = (int)(gq / LQ);

        float l[4];
        float mx = -1e30f;
        #pragma unroll
        for (int p = 0; p < 4; p++) { l[p] = logit[r][64 + h * 4 + p]; mx = fmaxf(mx, l[p]); }
        float s = 0.f;
        #pragma unroll
        for (int p = 0; p < 4; p++) { l[p] = expf(l[p] - mx); s += l[p]; }
        float inv = 1.0f / s;

        const int DIMS[4]  = {128, 64, 32, 16};
        const int START[4] = {0, 16384, 20480, 21504};
        #pragma unroll
        for (int lvl = 0; lvl < 4; lvl++) {
            float rx = refs[r][lvl][0];
            float ry = refs[r][lvl][1];
            int Wl = DIMS[lvl];
            #pragma unroll
            for (int p = 0; p < 4; p++) {
                float ox = logit[r][h * 8 + p * 2 + 0];
                float oy = logit[r][h * 8 + p * 2 + 1];
                float sx = fminf(fmaxf(rx + ox, 0.f), 1.f);
                float sy = fminf(fmaxf(ry + oy, 0.f), 1.f);
                int x0 = (int)floorf(sx * (float)(Wl - 1));
                int y0 = (int)floorf(sy * (float)(Wl - 1));
                vrow[r][h][p * 4 + lvl] = b * LQ + START[lvl] + y0 * Wl + x0;
                ws16[r][h][p * 4 + lvl] = l[p] * inv;
            }
        }
    }
    __syncthreads();

    // ---- gather: warp w -> rows 4w..4w+3; lane = head (lane>>2) x 8-ch group ----
    {
        const int w = t >> 5, lane = t & 31;
        const int h = lane >> 2;             // 0..7
        const int c8 = (lane & 3) * 8;       // channel group within head
        const int coff = h * 32 + c8;
        #pragma unroll
        for (int rw = 0; rw < 4; rw++) {
            const int r = w * 4 + rw;
            const int* vr = vrow[r][h];
            const float* wsv = ws16[r][h];
            float acc[8] = {0.f, 0.f, 0.f, 0.f, 0.f, 0.f, 0.f, 0.f};
            #pragma unroll
            for (int s = 0; s < 16; s++) {
                uint4 u = *(const uint4*)(g_val16 + (size_t)vr[s] * 256 + coff);
                float wgt = wsv[s];
                const __half2* hp = (const __half2*)&u;
                #pragma unroll
                for (int e = 0; e < 4; e++) {
                    float2 f = __half22float2(hp[e]);
                    acc[2 * e]     += wgt * f.x;
                    acc[2 * e + 1] += wgt * f.y;
                }
            }
            __half2 o[4];
            #pragma unroll
            for (int e = 0; e < 4; e++)
                o[e] = __floats2half2_rn(acc[2 * e], acc[2 * e + 1]);
            *(uint4*)(g_mid16 + (size_t)(gq0 + r) * 256 + coff) = *(uint4*)o;
        }
    }
}

// ----------------------------------------------------------------------------
extern "C" void kernel_launch(void* const* d_in, const int* in_sizes, int n_in,
                              void* d_out, int out_size)
{
    (void)in_sizes; (void)n_in; (void)out_size;
    const float* query  = (const float*)d_in[0];
    const float* refpts = (const float*)d_in[1];
    const float* f0     = (const float*)d_in[2];
    const float* f1     = (const float*)d_in[3];
    const float* f2     = (const float*)d_in[4];
    const float* f3     = (const float*)d_in[5];
    const float* W_off  = (const float*)d_in[6];
    const float* b_off  = (const float*)d_in[7];
    const float* W_attn = (const float*)d_in[8];
    const float* b_attn = (const float*)d_in[9];
    const float* W_val  = (const float*)d_in[10];
    const float* b_val  = (const float*)d_in[11];
    const float* W_out  = (const float*)d_in[12];
    const float* b_out  = (const float*)d_in[13];
    float* out = (float*)d_out;

    cudaFuncSetAttribute(gemm_mma<0>, cudaFuncAttributeMaxDynamicSharedMemorySize, SMEM_TOTAL);
    cudaFuncSetAttribute(gemm_mma<1>, cudaFuncAttributeMaxDynamicSharedMemorySize, SMEM_TOTAL);
    cudaFuncSetAttribute(gemm_mma<2>, cudaFuncAttributeMaxDynamicSharedMemorySize, SMEM_TOTAL);

    prep_kernel<<<256, 256>>>(W_val, W_out, W_off, W_attn, b_off, b_attn);

    dim3 g2(M_TOTAL / 64, 2);
    dim3 g1(M_TOTAL / 64, 1);
    // logits GEMM (query @ [W_off|W_attn|0]) -> g_logit
    gemm_mma<2><<<g1, 256, SMEM_TOTAL>>>(query, nullptr, nullptr, nullptr, nullptr, nullptr);
    // value projection -> g_val16
    gemm_mma<0><<<g2, 256, SMEM_TOTAL>>>(f0, f1, f2, f3, b_val, nullptr);
    // softmax + gather -> g_mid16
    sample_kernel<<<M_TOTAL / 32, 256>>>(refpts);
    // output projection -> out
    gemm_mma<1><<<g2, 256, SMEM_TOTAL>>>(nullptr, nullptr, nullptr, nullptr, b_out, out);
}

// round 10
// speedup vs baseline: 2.8941x; 1.0332x over previous
#include <cuda_runtime.h>
#include <cuda_bf16.h>
#include <cuda_fp16.h>
#include <cstdint>
#include <cstddef>

// ============================================================================
// DeformableAttention: B=4, Lq=21760, DIM=256, NH=8, NP=4, HD=32
// Levels: (128,128),(64,64),(32,32),(16,16) -> Lv = 21760, starts 0/16384/20480/21504
// M = B*Lq = B*Lv = 87040
// GEMMs: A fp16, W fp16 Dekker hi/lo, 2-term f16 MMA, fp32 accum.
// Sample + output projection FUSED (mid never leaves smem).
// ============================================================================

#define M_TOTAL 87040
#define LQ 21760

__device__ __half  g_val16[(size_t)M_TOTAL * 256];
__device__ float   g_logit[(size_t)M_TOTAL * 96];    // 0-63 off, 64-95 attn
// fp16 transposed hi/lo weights [slot][n*256+k]: 0=W_val, 1=W_out, 2=cat(W_off|W_attn|0)
__device__ __half  g_W16_hi[3][256 * 256];
__device__ __half  g_W16_lo[3][256 * 256];
__device__ float   g_bcat[128];

// ---------------------------------------------------------------------------
__device__ __forceinline__ uint32_t smem_to_u32(const void* p) {
    uint32_t a;
    asm("{ .reg .u64 t; cvta.to.shared.u64 t, %1; cvt.u32.u64 %0, t; }" : "=r"(a) : "l"(p));
    return a;
}
__device__ __forceinline__ uint32_t h2u(__half2 h) {
    return *reinterpret_cast<uint32_t*>(&h);
}
__device__ __forceinline__ void ldm_x4(uint32_t addr, uint32_t& r0, uint32_t& r1,
                                       uint32_t& r2, uint32_t& r3) {
    asm volatile("ldmatrix.sync.aligned.m8n8.x4.shared.b16 {%0,%1,%2,%3}, [%4];"
                 : "=r"(r0), "=r"(r1), "=r"(r2), "=r"(r3) : "r"(addr));
}
__device__ __forceinline__ void ldm_x2(uint32_t addr, uint32_t& r0, uint32_t& r1) {
    asm volatile("ldmatrix.sync.aligned.m8n8.x2.shared.b16 {%0,%1}, [%2];"
                 : "=r"(r0), "=r"(r1) : "r"(addr));
}
__device__ __forceinline__ void mma_f16(float* d, const uint32_t* a, const uint32_t* b) {
    asm volatile("mma.sync.aligned.m16n8k16.row.col.f32.f16.f16.f32 "
                 "{%0,%1,%2,%3}, {%4,%5,%6,%7}, {%8,%9}, {%0,%1,%2,%3};"
                 : "+f"(d[0]), "+f"(d[1]), "+f"(d[2]), "+f"(d[3])
                 : "r"(a[0]), "r"(a[1]), "r"(a[2]), "r"(a[3]), "r"(b[0]), "r"(b[1]));
}

// ---------------------------------------------------------------------------
// prep: transpose + fp16 Dekker split all weights; concatenated logit bias
// ---------------------------------------------------------------------------
__global__ void __launch_bounds__(256) prep_kernel(
    const float* __restrict__ Wv, const float* __restrict__ Wo,
    const float* __restrict__ Woff, const float* __restrict__ Wattn,
    const float* __restrict__ boff, const float* __restrict__ battn)
{
    int k = blockIdx.x;       // 0..255
    int n = threadIdx.x;      // 0..255
    {
        float v = Wv[k * 256 + n];
        __half h = __float2half_rn(v);
        g_W16_hi[0][n * 256 + k] = h;
        g_W16_lo[0][n * 256 + k] = __float2half_rn(v - __half2float(h));
    }
    {
        float v = Wo[k * 256 + n];
        __half h = __float2half_rn(v);
        g_W16_hi[1][n * 256 + k] = h;
        g_W16_lo[1][n * 256 + k] = __float2half_rn(v - __half2float(h));
    }
    if (n < 128) {
        float v = 0.f;
        if (n < 64)      v = Woff[k * 64 + n];
        else if (n < 96) v = Wattn[k * 32 + (n - 64)];
        __half h = __float2half_rn(v);
        g_W16_hi[2][n * 256 + k] = h;
        g_W16_lo[2][n * 256 + k] = __float2half_rn(v - __half2float(h));
        if (k == 0) {
            float bb = 0.f;
            if (n < 64)      bb = boff[n];
            else if (n < 96) bb = battn[n - 64];
            g_bcat[n] = bb;
        }
    }
}

// ---------------------------------------------------------------------------
// Input GEMMs. CTA tile M=64, N=128. K chunks of 64. 256 threads = 8 warps,
// warp tile 64x16. 2-term f16 MMA (W hi/lo).
// MODE 0: A = feats (fp32->f16)  -> g_val16 (fp16, +b_val) [grid.y=2]
// MODE 2: A = query (fp32->f16)  -> g_logit (ldc=96, +bcat; warps 6-7 skip mma)
// ---------------------------------------------------------------------------
#define STRB 144
#define SM_ROWPTR 0
#define SM_AHI 512
#define SM_BHI (SM_AHI + 64 * STRB)
#define SM_BLO (SM_BHI + 128 * STRB)
#define SMEM_TOTAL (SM_BLO + 128 * STRB)   // 46.6 KB

template<int MODE>
__global__ void __launch_bounds__(256, 3) gemm_mma(
    const float* __restrict__ f0, const float* __restrict__ f1,
    const float* __restrict__ f2, const float* __restrict__ f3,
    const float* __restrict__ bias)
{
    extern __shared__ char smem[];
    const int t = threadIdx.x;
    const int wid = t >> 5, lane = t & 31;
    const int m0 = blockIdx.x * 64;
    const int n0 = blockIdx.y * 128;

    const float** rowptr = (const float**)(smem + SM_ROWPTR);
    if (t < 64) {
        int r = m0 + t;
        const float* p;
        if (MODE == 0) {
            int b = r / LQ;
            int l = r - b * LQ;
            if (l < 16384)      p = f0 + ((size_t)b * 16384 + l) * 256;
            else if (l < 20480) p = f1 + ((size_t)b * 4096 + (l - 16384)) * 256;
            else if (l < 21504) p = f2 + ((size_t)b * 1024 + (l - 20480)) * 256;
            else                p = f3 + ((size_t)b * 256  + (l - 21504)) * 256;
        } else {
            p = f0 + (size_t)r * 256;   // query
        }
        rowptr[t] = p;
    }
    __syncthreads();

    const int slot = (MODE == 0) ? 0 : 2;
    const __half* WtH = g_W16_hi[slot];
    const __half* WtL = g_W16_lo[slot];

    uint32_t sb = smem_to_u32(smem);
    const uint32_t sAhi = sb + SM_AHI;
    const uint32_t sBhi = sb + SM_BHI, sBlo = sb + SM_BLO;

    const uint32_t a_row = lane & 15;
    const uint32_t a_koff = (lane >> 4) * 8;
    const uint32_t b_row = wid * 16 + (lane & 7);
    const uint32_t b_koff = ((lane >> 3) & 1) * 8;

    float acc[4][2][4];
    #pragma unroll
    for (int i = 0; i < 4; i++)
        #pragma unroll
        for (int j = 0; j < 2; j++)
            #pragma unroll
            for (int e = 0; e < 4; e++) acc[i][j][e] = 0.f;

    for (int c = 0; c < 4; c++) {
        // ---- A chunk: 64 rows x 64 k (fp32 -> fp16) ----
        #pragma unroll
        for (int i = 0; i < 4; i++) {
            int idx = t + i * 256;                // 1024 float4 slots
            int r = idx >> 4, c4 = (idx & 15) * 4;
            float4 v = *(const float4*)(rowptr[r] + c * 64 + c4);
            uint32_t h01 = h2u(__floats2half2_rn(v.x, v.y));
            uint32_t h23 = h2u(__floats2half2_rn(v.z, v.w));
            *(uint2*)(smem + SM_AHI + r * STRB + c4 * 2) = make_uint2(h01, h23);
        }
        // ---- B chunk: 128 n-rows x 64 k (hi + lo) ----
        #pragma unroll
        for (int i = 0; i < 4; i++) {
            int idx = t + i * 256;                // 1024 uint4 slots
            int r = idx >> 3, c8 = (idx & 7) * 8;
            size_t gofs = (size_t)(n0 + r) * 256 + c * 64 + c8;
            uint32_t off = r * STRB + c8 * 2;
            *(uint4*)(smem + SM_BHI + off) = *(const uint4*)(WtH + gofs);
            *(uint4*)(smem + SM_BLO + off) = *(const uint4*)(WtL + gofs);
        }
        __syncthreads();

        if (MODE != 2 || wid < 6) {
            #pragma unroll
            for (int ks = 0; ks < 4; ks++) {
                const int k0 = ks * 16;
                uint32_t a[4][4], bhi[2][2], blo[2][2];
                #pragma unroll
                for (int mt = 0; mt < 4; mt++) {
                    uint32_t off = (a_row + mt * 16) * STRB + (k0 + a_koff) * 2;
                    ldm_x4(sAhi + off, a[mt][0], a[mt][1], a[mt][2], a[mt][3]);
                }
                #pragma unroll
                for (int nt = 0; nt < 2; nt++) {
                    uint32_t off = (b_row + nt * 8) * STRB + (k0 + b_koff) * 2;
                    ldm_x2(sBhi + off, bhi[nt][0], bhi[nt][1]);
                    ldm_x2(sBlo + off, blo[nt][0], blo[nt][1]);
                }
                #pragma unroll
                for (int mt = 0; mt < 4; mt++)
                    #pragma unroll
                    for (int nt = 0; nt < 2; nt++) {
                        mma_f16(acc[mt][nt], a[mt], bhi[nt]);
                        mma_f16(acc[mt][nt], a[mt], blo[nt]);
                    }
            }
        }
        __syncthreads();
    }

    // ---- epilogue ----
    const int col_base = n0 + wid * 16;
    #pragma unroll
    for (int nt = 0; nt < 2; nt++) {
        const int col = col_base + nt * 8 + (lane & 3) * 2;
        if (MODE == 2 && col >= 96) continue;
        float2 bv;
        if (MODE == 2) bv = *(const float2*)(g_bcat + col);
        else           bv = *(const float2*)(bias + col);
        #pragma unroll
        for (int mt = 0; mt < 4; mt++) {
            int r0 = m0 + mt * 16 + (lane >> 2);
            float2 o0, o1;
            o0.x = acc[mt][nt][0] + bv.x; o0.y = acc[mt][nt][1] + bv.y;
            o1.x = acc[mt][nt][2] + bv.x; o1.y = acc[mt][nt][3] + bv.y;
            if (MODE == 0) {
                *(__half2*)(g_val16 + (size_t)r0 * 256 + col)       = __floats2half2_rn(o0.x, o0.y);
                *(__half2*)(g_val16 + (size_t)(r0 + 8) * 256 + col) = __floats2half2_rn(o1.x, o1.y);
            } else {
                *(float2*)(g_logit + (size_t)r0 * 96 + col)       = o0;
                *(float2*)(g_logit + (size_t)(r0 + 8) * 96 + col) = o1;
            }
        }
    }
}

// ----------------------------------------------------------------------------
// FUSED sample + output projection. Block = 64 queries, 256 threads.
// Phase A/B (2 halves of 32 rows): softmax + nearest index + gather, mid
// written into smem (fp16, ldmatrix layout). Phase C: out = mid @ W_out + b.
// 64 | LQ so the whole block shares one batch index -> uint16 sample rows.
// ----------------------------------------------------------------------------
#define ASTR 528                    // A row stride bytes (256 halves + 8 pad)
#define FS_A     0                  // 64 * 528 = 33792
#define FS_SCR   33792
#define FS_LOGIT (FS_SCR)           // 32*96*4 = 12288
#define FS_WS    (FS_SCR + 12288)   // 32*8*16*4 = 16384
#define FS_VROW  (FS_SCR + 28672)   // 32*8*16*2 = 8192
#define FS_REFS  (FS_SCR + 36864)   // 32*8*4 = 1024
#define FS_BHI   (FS_SCR)           // phase C alias: 128*144 = 18432
#define FS_BLO   (FS_SCR + 18432)   // ends at FS_SCR+36864
#define FUSED_SMEM (FS_SCR + 37888) // 71680 B

__global__ void __launch_bounds__(256, 3) fused_kernel(
    const float* __restrict__ refpts,
    const float* __restrict__ bout,
    float* __restrict__ out)
{
    extern __shared__ char smem[];
    const int t = threadIdx.x;
    const int wid = t >> 5, lane = t & 31;
    const long long gq0 = (long long)blockIdx.x * 64;
    const int b = (int)(gq0 / LQ);            // constant per block (64 | LQ)

    float (*logit)[96]    = (float (*)[96])(smem + FS_LOGIT);
    float (*ws)[8][16]    = (float (*)[8][16])(smem + FS_WS);
    uint16_t (*vrl)[8][16] = (uint16_t (*)[8][16])(smem + FS_VROW);
    float (*refs)[4][2]   = (float (*)[4][2])(smem + FS_REFS);

    // ================= Phase A/B: sample 2 halves of 32 rows =================
    for (int half = 0; half < 2; half++) {
        const long long q0 = gq0 + half * 32;

        #pragma unroll
        for (int i = 0; i < 3; i++) {
            int idx = t + i * 256;            // 768 float4 slots
            int r = idx / 24, cq = (idx % 24) * 4;
            *(float4*)&logit[r][cq] = *(const float4*)(g_logit + (q0 + r) * 96 + cq);
        }
        ((float*)refs)[t] = refpts[q0 * 8 + t];
        __syncthreads();

        // softmax + indices: thread -> (row, head)
        {
            const int r = t >> 3, h = t & 7;
            float l[4];
            float mx = -1e30f;
            #pragma unroll
            for (int p = 0; p < 4; p++) { l[p] = logit[r][64 + h * 4 + p]; mx = fmaxf(mx, l[p]); }
            float s = 0.f;
            #pragma unroll
            for (int p = 0; p < 4; p++) { l[p] = expf(l[p] - mx); s += l[p]; }
            float inv = 1.0f / s;

            const int DIMS[4]  = {128, 64, 32, 16};
            const int START[4] = {0, 16384, 20480, 21504};
            #pragma unroll
            for (int lvl = 0; lvl < 4; lvl++) {
                float rx = refs[r][lvl][0];
                float ry = refs[r][lvl][1];
                int Wl = DIMS[lvl];
                #pragma unroll
                for (int p = 0; p < 4; p++) {
                    float ox = logit[r][h * 8 + p * 2 + 0];
                    float oy = logit[r][h * 8 + p * 2 + 1];
                    float sx = fminf(fmaxf(rx + ox, 0.f), 1.f);
                    float sy = fminf(fmaxf(ry + oy, 0.f), 1.f);
                    int x0 = (int)floorf(sx * (float)(Wl - 1));
                    int y0 = (int)floorf(sy * (float)(Wl - 1));
                    vrl[r][h][p * 4 + lvl] = (uint16_t)(START[lvl] + y0 * Wl + x0);
                    ws[r][h][p * 4 + lvl] = l[p] * inv;
                }
            }
        }
        __syncthreads();

        // gather -> mid into A-smem (fp16, row-major stride ASTR)
        {
            const int h = lane >> 2;             // 0..7
            const int c8 = (lane & 3) * 8;       // channel group within head
            const int coff = h * 32 + c8;
            const size_t vbase = (size_t)b * LQ;
            #pragma unroll
            for (int rw = 0; rw < 4; rw++) {
                const int r = wid * 4 + rw;
                const uint16_t* vr = vrl[r][h];
                const float* wsv = ws[r][h];
                float acc[8] = {0.f, 0.f, 0.f, 0.f, 0.f, 0.f, 0.f, 0.f};
                #pragma unroll
                for (int s = 0; s < 16; s++) {
                    uint4 u = *(const uint4*)(g_val16 + (vbase + vr[s]) * 256 + coff);
                    float wgt = wsv[s];
                    const __half2* hp = (const __half2*)&u;
                    #pragma unroll
                    for (int e = 0; e < 4; e++) {
                        float2 f = __half22float2(hp[e]);
                        acc[2 * e]     += wgt * f.x;
                        acc[2 * e + 1] += wgt * f.y;
                    }
                }
                __half2 o[4];
                #pragma unroll
                for (int e = 0; e < 4; e++)
                    o[e] = __floats2half2_rn(acc[2 * e], acc[2 * e + 1]);
                *(uint4*)(smem + FS_A + (half * 32 + r) * ASTR + coff * 2) = *(uint4*)o;
            }
        }
        __syncthreads();   // protect scratch reuse / A writes
    }

    // ================= Phase C: out = mid @ W_out + b_out =================
    uint32_t sb = smem_to_u32(smem);
    const uint32_t sA = sb + FS_A;
    const uint32_t sBhi = sb + FS_BHI, sBlo = sb + FS_BLO;
    const __half* WtH = g_W16_hi[1];
    const __half* WtL = g_W16_lo[1];

    const uint32_t a_row = lane & 15;
    const uint32_t a_koff = (lane >> 4) * 8;
    const uint32_t b_row = wid * 16 + (lane & 7);
    const uint32_t b_koff = ((lane >> 3) & 1) * 8;
    const int m0 = (int)gq0;

    for (int nh = 0; nh < 2; nh++) {
        const int n0 = nh * 128;
        float acc[4][2][4];
        #pragma unroll
        for (int i = 0; i < 4; i++)
            #pragma unroll
            for (int j = 0; j < 2; j++)
                #pragma unroll
                for (int e = 0; e < 4; e++) acc[i][j][e] = 0.f;

        for (int c = 0; c < 4; c++) {
            #pragma unroll
            for (int i = 0; i < 4; i++) {
                int idx = t + i * 256;                // 1024 uint4 slots
                int r = idx >> 3, c8 = (idx & 7) * 8;
                size_t gofs = (size_t)(n0 + r) * 256 + c * 64 + c8;
                uint32_t off = r * STRB + c8 * 2;
                *(uint4*)(smem + FS_BHI + off) = *(const uint4*)(WtH + gofs);
                *(uint4*)(smem + FS_BLO + off) = *(const uint4*)(WtL + gofs);
            }
            __syncthreads();

            #pragma unroll
            for (int ks = 0; ks < 4; ks++) {
                const int k0 = c * 64 + ks * 16;
                uint32_t a[4][4], bhi[2][2], blo[2][2];
                #pragma unroll
                for (int mt = 0; mt < 4; mt++) {
                    uint32_t off = (a_row + mt * 16) * ASTR + (k0 + a_koff) * 2;
                    ldm_x4(sA + off, a[mt][0], a[mt][1], a[mt][2], a[mt][3]);
                }
                #pragma unroll
                for (int nt = 0; nt < 2; nt++) {
                    uint32_t off = (b_row + nt * 8) * STRB + (ks * 16 + b_koff) * 2;
                    ldm_x2(sBhi + off, bhi[nt][0], bhi[nt][1]);
                    ldm_x2(sBlo + off, blo[nt][0], blo[nt][1]);
                }
                #pragma unroll
                for (int mt = 0; mt < 4; mt++)
                    #pragma unroll
                    for (int nt = 0; nt < 2; nt++) {
                        mma_f16(acc[mt][nt], a[mt], bhi[nt]);
                        mma_f16(acc[mt][nt], a[mt], blo[nt]);
                    }
            }
            __syncthreads();
        }

        // epilogue for this n-half
        const int col_base = n0 + wid * 16;
        #pragma unroll
        for (int nt = 0; nt < 2; nt++) {
            const int col = col_base + nt * 8 + (lane & 3) * 2;
            float2 bv = *(const float2*)(bout + col);
            #pragma unroll
            for (int mt = 0; mt < 4; mt++) {
                int r0 = m0 + mt * 16 + (lane >> 2);
                float2 o0, o1;
                o0.x = acc[mt][nt][0] + bv.x; o0.y = acc[mt][nt][1] + bv.y;
                o1.x = acc[mt][nt][2] + bv.x; o1.y = acc[mt][nt][3] + bv.y;
                *(float2*)(out + (size_t)r0 * 256 + col)       = o0;
                *(float2*)(out + (size_t)(r0 + 8) * 256 + col) = o1;
            }
        }
    }
}

// ----------------------------------------------------------------------------
extern "C" void kernel_launch(void* const* d_in, const int* in_sizes, int n_in,
                              void* d_out, int out_size)
{
    (void)in_sizes; (void)n_in; (void)out_size;
    const float* query  = (const float*)d_in[0];
    const float* refpts = (const float*)d_in[1];
    const float* f0     = (const float*)d_in[2];
    const float* f1     = (const float*)d_in[3];
    const float* f2     = (const float*)d_in[4];
    const float* f3     = (const float*)d_in[5];
    const float* W_off  = (const float*)d_in[6];
    const float* b_off  = (const float*)d_in[7];
    const float* W_attn = (const float*)d_in[8];
    const float* b_attn = (const float*)d_in[9];
    const float* W_val  = (const float*)d_in[10];
    const float* b_val  = (const float*)d_in[11];
    const float* W_out  = (const float*)d_in[12];
    const float* b_out  = (const float*)d_in[13];
    float* out = (float*)d_out;

    cudaFuncSetAttribute(gemm_mma<0>, cudaFuncAttributeMaxDynamicSharedMemorySize, SMEM_TOTAL);
    cudaFuncSetAttribute(gemm_mma<2>, cudaFuncAttributeMaxDynamicSharedMemorySize, SMEM_TOTAL);
    cudaFuncSetAttribute(fused_kernel, cudaFuncAttributeMaxDynamicSharedMemorySize, FUSED_SMEM);

    prep_kernel<<<256, 256>>>(W_val, W_out, W_off, W_attn, b_off, b_attn);

    // logits GEMM (query @ [W_off|W_attn|0]) -> g_logit
    gemm_mma<2><<<dim3(M_TOTAL / 64, 1), 256, SMEM_TOTAL>>>(query, nullptr, nullptr, nullptr, nullptr);
    // value projection -> g_val16
    gemm_mma<0><<<dim3(M_TOTAL / 64, 2), 256, SMEM_TOTAL>>>(f0, f1, f2, f3, b_val);
    // fused softmax + gather + output projection -> out
    fused_kernel<<<M_TOTAL / 64, 256, FUSED_SMEM>>>(refpts, b_out, out);
}